// round 1
// baseline (speedup 1.0000x reference)
#include <cuda_runtime.h>
#include <math.h>

#define BB 16
#define TT 28
#define HH 16
#define WW 16
#define CE 24
#define FF 64
#define GG 256   // 4F gates
#define C2 128   // 2F concat
#define TIN 112
#define CIN 6

// ---------------- scratch (static device globals; no allocs) ----------------
__device__ float g_xe  [BB*TT*HH*WW*CE];   // embedded input
__device__ float g_xz0f[BB*TT*HH*WW*GG];   // layer0 fwd input-conv
__device__ float g_xz0b[BB*TT*HH*WW*GG];   // layer0 bwd input-conv
__device__ float g_h0  [BB*TT*HH*WW*C2];   // layer0 output (concat)
__device__ float g_xz1f[BB*TT*HH*WW*GG];
__device__ float g_xz1b[BB*TT*HH*WW*GG];
__device__ float g_h1  [BB*TT*HH*WW*C2];
__device__ float g_hst [2][2*BB*HH*WW*FF]; // double-buffered hidden state (2 dirs)
__device__ float g_cst [2*BB*HH*WW*FF];    // cell state (2 dirs)

// ---------------- embed: [B,Tin,H,W,6] -> [B,T,H,W,24] ----------------
__global__ void embed_kernel(const float* __restrict__ x) {
    int idx = blockIdx.x * blockDim.x + threadIdx.x;
    const int total = BB*TT*HH*WW*CE;
    if (idx >= total) return;
    int c = idx % CE;
    int w = (idx / CE) % WW;
    int h = (idx / (CE*WW)) % HH;
    int t = (idx / (CE*WW*HH)) % TT;
    int b = idx / (CE*WW*HH*TT);
    int flat = t*CE + c;
    int tin = flat / CIN;
    int cin = flat % CIN;
    g_xe[idx] = x[(((size_t)(b*TIN + tin)*HH + h)*WW + w)*CIN + cin];
}

// ---------------- generic input conv: NHWC, 3x3 same, OC=256 ----------------
// One block = one (image, row). 256 threads, thread = output channel.
// 16-pixel row of accumulators; weights broadcast-loaded, reused across pixels.
template<int IC>
__global__ void __launch_bounds__(256)
conv_in_kernel(const float* __restrict__ in,
               const float* __restrict__ wgt,
               const float* __restrict__ bias,
               float* __restrict__ out) {
    __shared__ float sh[3*WW*IC];
    int n = blockIdx.x / HH;
    int h = blockIdx.x % HH;
    int tid = threadIdx.x;
    const float* img = in + (size_t)n * HH * WW * IC;

    for (int i = tid; i < 3*WW*IC; i += 256) {
        int r = i / (WW*IC);
        int row = h - 1 + r;
        float v = 0.f;
        if (row >= 0 && row < HH) v = img[row*WW*IC + (i - r*WW*IC)];
        sh[i] = v;
    }
    __syncthreads();

    int oc = tid;
    float acc[WW];
    float bv = bias[oc];
    #pragma unroll
    for (int p = 0; p < WW; p++) acc[p] = bv;

    for (int kh = 0; kh < 3; kh++) {
        for (int ic = 0; ic < IC; ic++) {
            float rv[WW+2];
            rv[0] = 0.f; rv[WW+1] = 0.f;
            #pragma unroll
            for (int w = 0; w < WW; w++) rv[w+1] = sh[(kh*WW + w)*IC + ic];
            #pragma unroll
            for (int kw = 0; kw < 3; kw++) {
                float wv = wgt[((kh*3 + kw)*IC + ic)*GG + oc];
                #pragma unroll
                for (int p = 0; p < WW; p++) acc[p] += rv[p+kw] * wv;
            }
        }
    }
    float* op = out + (size_t)(n*HH + h)*WW*GG + oc;
    #pragma unroll
    for (int p = 0; p < WW; p++) op[p*GG] = acc[p];
}

// ---------------- zero the read-side hidden state + cell state ----------------
__global__ void zero_states() {
    int idx = blockIdx.x * blockDim.x + threadIdx.x;
    const int n = 2*BB*HH*WW*FF;
    if (idx < n) { g_hst[0][idx] = 0.f; g_cst[idx] = 0.f; }
}

// ---------------- one recurrent step, both directions ----------------
// Block = (dir, batch, row). Phase 1: hidden conv + xz into shared gate tile.
// Phase 2: gate nonlinearities, c/h update, write h to state + output sequence.
__global__ void __launch_bounds__(256)
lstm_step_kernel(const float* __restrict__ xzf,
                 const float* __restrict__ xzb,
                 const float* __restrict__ whf,
                 const float* __restrict__ whb,
                 float* __restrict__ hseq,
                 int s) {
    __shared__ float sh[3*WW*FF];   // h_prev halo rows (12KB)
    __shared__ float zs[WW*GG];     // gate exchange   (16KB)

    int bid = blockIdx.x;
    int dir = bid / (BB*HH);
    int rem = bid % (BB*HH);
    int b = rem / HH;
    int h = rem % HH;
    int tid = threadIdx.x;

    int t_out = (dir == 0) ? s : (TT - 1 - s);
    const float* xz = (dir == 0) ? xzf : xzb;
    const float* wh = (dir == 0) ? whf : whb;
    const float* hprev = g_hst[s & 1] + (size_t)(dir*BB + b)*HH*WW*FF;

    for (int i = tid; i < 3*WW*FF; i += 256) {
        int r = i / (WW*FF);
        int row = h - 1 + r;
        float v = 0.f;
        if (row >= 0 && row < HH) v = hprev[row*WW*FF + (i - r*WW*FF)];
        sh[i] = v;
    }
    __syncthreads();

    int oc = tid;
    float acc[WW];
    {
        const float* xp = xz + (size_t)((b*TT + t_out)*HH + h)*WW*GG + oc;
        #pragma unroll
        for (int p = 0; p < WW; p++) acc[p] = xp[p*GG];
    }
    for (int kh = 0; kh < 3; kh++) {
        for (int ic = 0; ic < FF; ic++) {
            float rv[WW+2];
            rv[0] = 0.f; rv[WW+1] = 0.f;
            #pragma unroll
            for (int w = 0; w < WW; w++) rv[w+1] = sh[(kh*WW + w)*FF + ic];
            #pragma unroll
            for (int kw = 0; kw < 3; kw++) {
                float wv = wh[((kh*3 + kw)*FF + ic)*GG + oc];
                #pragma unroll
                for (int p = 0; p < WW; p++) acc[p] += rv[p+kw] * wv;
            }
        }
    }
    #pragma unroll
    for (int p = 0; p < WW; p++) zs[p*GG + oc] = acc[p];
    __syncthreads();

    // phase 2: 256 threads = 64 feature channels x 4 pixel groups
    int f  = tid % FF;
    int pg = tid / FF;
    float* cst  = g_cst             + (size_t)(dir*BB + b)*HH*WW*FF + h*WW*FF;
    float* hnew = g_hst[(s+1) & 1]  + (size_t)(dir*BB + b)*HH*WW*FF + h*WW*FF;
    float* hs   = hseq + (size_t)((b*TT + t_out)*HH + h)*WW*C2 + dir*FF + f;
    #pragma unroll
    for (int q = 0; q < 4; q++) {
        int p = pg*4 + q;
        float iv = zs[p*GG +        f];
        float fv = zs[p*GG +   FF + f];
        float gv = zs[p*GG + 2*FF + f];
        float ov = zs[p*GG + 3*FF + f];
        iv = 1.f / (1.f + __expf(-iv));
        fv = 1.f / (1.f + __expf(-fv));
        gv = tanhf(gv);
        ov = 1.f / (1.f + __expf(-ov));
        float c = fv * cst[p*FF + f] + iv * gv;
        cst[p*FF + f] = c;
        float hv = ov * tanhf(c);
        hnew[p*FF + f] = hv;
        hs[p*C2] = hv;
    }
}

// ---------------- output conv: [B*T,H,W,128] -> [B*T,H,W,1] ----------------
__global__ void __launch_bounds__(256)
out_conv_kernel(const float* __restrict__ wgt,
                const float* __restrict__ bias,
                float* __restrict__ out) {
    __shared__ float sh[3*WW*C2];   // 24KB
    __shared__ float ps[WW*16];
    int n = blockIdx.x / HH;
    int h = blockIdx.x % HH;
    int tid = threadIdx.x;
    const float* img = g_h1 + (size_t)n * HH * WW * C2;

    for (int i = tid; i < 3*WW*C2; i += 256) {
        int r = i / (WW*C2);
        int row = h - 1 + r;
        float v = 0.f;
        if (row >= 0 && row < HH) v = img[row*WW*C2 + (i - r*WW*C2)];
        sh[i] = v;
    }
    __syncthreads();

    int p = tid / 16;
    int q = tid % 16;          // covers ic = q*8 .. q*8+7
    float partial = 0.f;
    for (int kh = 0; kh < 3; kh++) {
        for (int kw = 0; kw < 3; kw++) {
            int iw = p + kw - 1;
            if (iw < 0 || iw >= WW) continue;
            #pragma unroll
            for (int j = 0; j < 8; j++) {
                int ic = q*8 + j;
                partial += sh[(kh*WW + iw)*C2 + ic] * wgt[(kh*3 + kw)*C2 + ic];
            }
        }
    }
    ps[tid] = partial;
    __syncthreads();
    if (q == 0) {
        float sum = bias[0];
        #pragma unroll
        for (int j = 0; j < 16; j++) sum += ps[p*16 + j];
        out[(size_t)(n*HH + h)*WW + p] = sum;
    }
}

// ---------------- launch ----------------
extern "C" void kernel_launch(void* const* d_in, const int* in_sizes, int n_in,
                              void* d_out, int out_size) {
    const float* x    = (const float*)d_in[0];
    const float* wx0f = (const float*)d_in[1];
    const float* wh0f = (const float*)d_in[2];
    const float* b0f  = (const float*)d_in[3];
    const float* wx0b = (const float*)d_in[4];
    const float* wh0b = (const float*)d_in[5];
    const float* b0b  = (const float*)d_in[6];
    const float* wx1f = (const float*)d_in[7];
    const float* wh1f = (const float*)d_in[8];
    const float* b1f  = (const float*)d_in[9];
    const float* wx1b = (const float*)d_in[10];
    const float* wh1b = (const float*)d_in[11];
    const float* b1b  = (const float*)d_in[12];
    const float* wout = (const float*)d_in[13];
    const float* bout = (const float*)d_in[14];
    float* out = (float*)d_out;

    // scratch addresses (host-side symbol lookup; no allocation, capture-safe)
    float *p_xe, *p_xz0f, *p_xz0b, *p_h0, *p_xz1f, *p_xz1b, *p_h1;
    cudaGetSymbolAddress((void**)&p_xe,   g_xe);
    cudaGetSymbolAddress((void**)&p_xz0f, g_xz0f);
    cudaGetSymbolAddress((void**)&p_xz0b, g_xz0b);
    cudaGetSymbolAddress((void**)&p_h0,   g_h0);
    cudaGetSymbolAddress((void**)&p_xz1f, g_xz1f);
    cudaGetSymbolAddress((void**)&p_xz1b, g_xz1b);
    cudaGetSymbolAddress((void**)&p_h1,   g_h1);

    const int NI = BB*TT;                 // 448 images per "timestep batch"
    const int totalE = BB*TT*HH*WW*CE;
    const int nState = 2*BB*HH*WW*FF;

    embed_kernel<<<(totalE + 255)/256, 256>>>(x);

    // ----- layer 0 -----
    conv_in_kernel<CE><<<NI*HH, 256>>>(p_xe, wx0f, b0f, p_xz0f);
    conv_in_kernel<CE><<<NI*HH, 256>>>(p_xe, wx0b, b0b, p_xz0b);
    zero_states<<<(nState + 255)/256, 256>>>();
    for (int s = 0; s < TT; s++)
        lstm_step_kernel<<<2*BB*HH, 256>>>(p_xz0f, p_xz0b, wh0f, wh0b, p_h0, s);

    // ----- layer 1 -----
    conv_in_kernel<C2><<<NI*HH, 256>>>(p_h0, wx1f, b1f, p_xz1f);
    conv_in_kernel<C2><<<NI*HH, 256>>>(p_h0, wx1b, b1b, p_xz1b);
    zero_states<<<(nState + 255)/256, 256>>>();
    for (int s = 0; s < TT; s++)
        lstm_step_kernel<<<2*BB*HH, 256>>>(p_xz1f, p_xz1b, wh1f, wh1b, p_h1, s);

    // ----- output conv -----
    out_conv_kernel<<<NI*HH, 256>>>(wout, bout, out);
}

// round 2
// speedup vs baseline: 1.0832x; 1.0832x over previous
#include <cuda_runtime.h>
#include <math.h>

#define BB 16
#define TT 28
#define HH 16
#define WW 16
#define CE 24
#define FF 64
#define GG 256   // 4F gates
#define C2 128   // 2F concat
#define TIN 112
#define CIN 6

// ---------------- scratch (static device globals; no allocs) ----------------
__device__ float g_xe  [BB*TT*HH*WW*CE];   // embedded input
__device__ float g_xz0f[BB*TT*HH*WW*GG];   // layer0 fwd input-conv
__device__ float g_xz0b[BB*TT*HH*WW*GG];   // layer0 bwd input-conv
__device__ float g_h0  [BB*TT*HH*WW*C2];   // layer0 output (concat)
__device__ float g_xz1f[BB*TT*HH*WW*GG];
__device__ float g_xz1b[BB*TT*HH*WW*GG];
__device__ float g_h1  [BB*TT*HH*WW*C2];
__device__ float g_hst [2][2*BB*HH*WW*FF]; // double-buffered hidden state (2 dirs)
__device__ float g_cst [2*BB*HH*WW*FF];    // cell state (2 dirs)

// ---------------- embed: [B,Tin,H,W,6] -> [B,T,H,W,24] ----------------
__global__ void embed_kernel(const float* __restrict__ x) {
    int idx = blockIdx.x * blockDim.x + threadIdx.x;
    const int total = BB*TT*HH*WW*CE;
    if (idx >= total) return;
    int c = idx % CE;
    int w = (idx / CE) % WW;
    int h = (idx / (CE*WW)) % HH;
    int t = (idx / (CE*WW*HH)) % TT;
    int b = idx / (CE*WW*HH*TT);
    int flat = t*CE + c;
    int tin = flat / CIN;
    int cin = flat % CIN;
    g_xe[idx] = x[(((size_t)(b*TIN + tin)*HH + h)*WW + w)*CIN + cin];
}

// ---------------- generic input conv: NHWC, 3x3 same, OC=256 ----------------
// One block = one (image, row). 256 threads, thread = output channel.
// 16-pixel row of accumulators; weights broadcast-loaded, reused across pixels.
template<int IC>
__global__ void __launch_bounds__(256)
conv_in_kernel(const float* __restrict__ in,
               const float* __restrict__ wgt,
               const float* __restrict__ bias,
               float* __restrict__ out) {
    __shared__ float sh[3*WW*IC];
    int n = blockIdx.x / HH;
    int h = blockIdx.x % HH;
    int tid = threadIdx.x;
    const float* img = in + (size_t)n * HH * WW * IC;

    for (int i = tid; i < 3*WW*IC; i += 256) {
        int r = i / (WW*IC);
        int row = h - 1 + r;
        float v = 0.f;
        if (row >= 0 && row < HH) v = img[row*WW*IC + (i - r*WW*IC)];
        sh[i] = v;
    }
    __syncthreads();

    int oc = tid;
    float acc[WW];
    float bv = bias[oc];
    #pragma unroll
    for (int p = 0; p < WW; p++) acc[p] = bv;

    for (int kh = 0; kh < 3; kh++) {
        for (int ic = 0; ic < IC; ic++) {
            float rv[WW+2];
            rv[0] = 0.f; rv[WW+1] = 0.f;
            #pragma unroll
            for (int w = 0; w < WW; w++) rv[w+1] = sh[(kh*WW + w)*IC + ic];
            #pragma unroll
            for (int kw = 0; kw < 3; kw++) {
                float wv = wgt[((kh*3 + kw)*IC + ic)*GG + oc];
                #pragma unroll
                for (int p = 0; p < WW; p++) acc[p] += rv[p+kw] * wv;
            }
        }
    }
    float* op = out + (size_t)(n*HH + h)*WW*GG + oc;
    #pragma unroll
    for (int p = 0; p < WW; p++) op[p*GG] = acc[p];
}

// ---------------- zero the read-side hidden state + cell state ----------------
__global__ void zero_states() {
    int idx = blockIdx.x * blockDim.x + threadIdx.x;
    const int n = 2*BB*HH*WW*FF;
    if (idx < n) { g_hst[0][idx] = 0.f; g_cst[idx] = 0.f; }
}

// ---------------- one recurrent step, both directions ----------------
// Block = (dir, batch, row). Phase 1: hidden conv + xz into shared gate tile.
// Phase 2: gate nonlinearities, c/h update, write h to state + output sequence.
__global__ void __launch_bounds__(256)
lstm_step_kernel(const float* __restrict__ xzf,
                 const float* __restrict__ xzb,
                 const float* __restrict__ whf,
                 const float* __restrict__ whb,
                 float* __restrict__ hseq,
                 int s) {
    __shared__ float sh[3*WW*FF];   // h_prev halo rows (12KB)
    __shared__ float zs[WW*GG];     // gate exchange   (16KB)

    int bid = blockIdx.x;
    int dir = bid / (BB*HH);
    int rem = bid % (BB*HH);
    int b = rem / HH;
    int h = rem % HH;
    int tid = threadIdx.x;

    int t_out = (dir == 0) ? s : (TT - 1 - s);
    const float* xz = (dir == 0) ? xzf : xzb;
    const float* wh = (dir == 0) ? whf : whb;
    const float* hprev = g_hst[s & 1] + (size_t)(dir*BB + b)*HH*WW*FF;

    for (int i = tid; i < 3*WW*FF; i += 256) {
        int r = i / (WW*FF);
        int row = h - 1 + r;
        float v = 0.f;
        if (row >= 0 && row < HH) v = hprev[row*WW*FF + (i - r*WW*FF)];
        sh[i] = v;
    }
    __syncthreads();

    int oc = tid;
    float acc[WW];
    {
        const float* xp = xz + (size_t)((b*TT + t_out)*HH + h)*WW*GG + oc;
        #pragma unroll
        for (int p = 0; p < WW; p++) acc[p] = xp[p*GG];
    }
    for (int kh = 0; kh < 3; kh++) {
        for (int ic = 0; ic < FF; ic++) {
            float rv[WW+2];
            rv[0] = 0.f; rv[WW+1] = 0.f;
            #pragma unroll
            for (int w = 0; w < WW; w++) rv[w+1] = sh[(kh*WW + w)*FF + ic];
            #pragma unroll
            for (int kw = 0; kw < 3; kw++) {
                float wv = wh[((kh*3 + kw)*FF + ic)*GG + oc];
                #pragma unroll
                for (int p = 0; p < WW; p++) acc[p] += rv[p+kw] * wv;
            }
        }
    }
    #pragma unroll
    for (int p = 0; p < WW; p++) zs[p*GG + oc] = acc[p];
    __syncthreads();

    // phase 2: 256 threads = 64 feature channels x 4 pixel groups
    int f  = tid % FF;
    int pg = tid / FF;
    float* cst  = g_cst             + (size_t)(dir*BB + b)*HH*WW*FF + h*WW*FF;
    float* hnew = g_hst[(s+1) & 1]  + (size_t)(dir*BB + b)*HH*WW*FF + h*WW*FF;
    float* hs   = hseq + (size_t)((b*TT + t_out)*HH + h)*WW*C2 + dir*FF + f;
    #pragma unroll
    for (int q = 0; q < 4; q++) {
        int p = pg*4 + q;
        float iv = zs[p*GG +        f];
        float fv = zs[p*GG +   FF + f];
        float gv = zs[p*GG + 2*FF + f];
        float ov = zs[p*GG + 3*FF + f];
        iv = 1.f / (1.f + __expf(-iv));
        fv = 1.f / (1.f + __expf(-fv));
        gv = tanhf(gv);
        ov = 1.f / (1.f + __expf(-ov));
        float c = fv * cst[p*FF + f] + iv * gv;
        cst[p*FF + f] = c;
        float hv = ov * tanhf(c);
        hnew[p*FF + f] = hv;
        hs[p*C2] = hv;
    }
}

// ---------------- output conv: [B*T,H,W,128] -> [B*T,H,W,1] ----------------
__global__ void __launch_bounds__(256)
out_conv_kernel(const float* __restrict__ wgt,
                const float* __restrict__ bias,
                float* __restrict__ out) {
    __shared__ float sh[3*WW*C2];   // 24KB
    __shared__ float ps[WW*16];
    int n = blockIdx.x / HH;
    int h = blockIdx.x % HH;
    int tid = threadIdx.x;
    const float* img = g_h1 + (size_t)n * HH * WW * C2;

    for (int i = tid; i < 3*WW*C2; i += 256) {
        int r = i / (WW*C2);
        int row = h - 1 + r;
        float v = 0.f;
        if (row >= 0 && row < HH) v = img[row*WW*C2 + (i - r*WW*C2)];
        sh[i] = v;
    }
    __syncthreads();

    int p = tid / 16;
    int q = tid % 16;          // covers ic = q*8 .. q*8+7
    float partial = 0.f;
    for (int kh = 0; kh < 3; kh++) {
        for (int kw = 0; kw < 3; kw++) {
            int iw = p + kw - 1;
            if (iw < 0 || iw >= WW) continue;
            #pragma unroll
            for (int j = 0; j < 8; j++) {
                int ic = q*8 + j;
                partial += sh[(kh*WW + iw)*C2 + ic] * wgt[(kh*3 + kw)*C2 + ic];
            }
        }
    }
    ps[tid] = partial;
    __syncthreads();
    if (q == 0) {
        float sum = bias[0];
        #pragma unroll
        for (int j = 0; j < 16; j++) sum += ps[p*16 + j];
        out[(size_t)(n*HH + h)*WW + p] = sum;
    }
}

// ---------------- launch ----------------
extern "C" void kernel_launch(void* const* d_in, const int* in_sizes, int n_in,
                              void* d_out, int out_size) {
    const float* x    = (const float*)d_in[0];
    const float* wx0f = (const float*)d_in[1];
    const float* wh0f = (const float*)d_in[2];
    const float* b0f  = (const float*)d_in[3];
    const float* wx0b = (const float*)d_in[4];
    const float* wh0b = (const float*)d_in[5];
    const float* b0b  = (const float*)d_in[6];
    const float* wx1f = (const float*)d_in[7];
    const float* wh1f = (const float*)d_in[8];
    const float* b1f  = (const float*)d_in[9];
    const float* wx1b = (const float*)d_in[10];
    const float* wh1b = (const float*)d_in[11];
    const float* b1b  = (const float*)d_in[12];
    const float* wout = (const float*)d_in[13];
    const float* bout = (const float*)d_in[14];
    float* out = (float*)d_out;

    // scratch addresses (host-side symbol lookup; no allocation, capture-safe)
    float *p_xe, *p_xz0f, *p_xz0b, *p_h0, *p_xz1f, *p_xz1b, *p_h1;
    cudaGetSymbolAddress((void**)&p_xe,   g_xe);
    cudaGetSymbolAddress((void**)&p_xz0f, g_xz0f);
    cudaGetSymbolAddress((void**)&p_xz0b, g_xz0b);
    cudaGetSymbolAddress((void**)&p_h0,   g_h0);
    cudaGetSymbolAddress((void**)&p_xz1f, g_xz1f);
    cudaGetSymbolAddress((void**)&p_xz1b, g_xz1b);
    cudaGetSymbolAddress((void**)&p_h1,   g_h1);

    const int NI = BB*TT;                 // 448 images per "timestep batch"
    const int totalE = BB*TT*HH*WW*CE;
    const int nState = 2*BB*HH*WW*FF;

    embed_kernel<<<(totalE + 255)/256, 256>>>(x);

    // ----- layer 0 -----
    conv_in_kernel<CE><<<NI*HH, 256>>>(p_xe, wx0f, b0f, p_xz0f);
    conv_in_kernel<CE><<<NI*HH, 256>>>(p_xe, wx0b, b0b, p_xz0b);
    zero_states<<<(nState + 255)/256, 256>>>();
    for (int s = 0; s < TT; s++)
        lstm_step_kernel<<<2*BB*HH, 256>>>(p_xz0f, p_xz0b, wh0f, wh0b, p_h0, s);

    // ----- layer 1 -----
    conv_in_kernel<C2><<<NI*HH, 256>>>(p_h0, wx1f, b1f, p_xz1f);
    conv_in_kernel<C2><<<NI*HH, 256>>>(p_h0, wx1b, b1b, p_xz1b);
    zero_states<<<(nState + 255)/256, 256>>>();
    for (int s = 0; s < TT; s++)
        lstm_step_kernel<<<2*BB*HH, 256>>>(p_xz1f, p_xz1b, wh1f, wh1b, p_h1, s);

    // ----- output conv -----
    out_conv_kernel<<<NI*HH, 256>>>(wout, bout, out);
}

// round 5
// speedup vs baseline: 2.8836x; 2.6621x over previous
#include <cuda_runtime.h>
#include <cuda_bf16.h>
#include <stdint.h>
#include <math.h>

typedef __nv_bfloat16 bf16;

#define NIMG 448
#define TAPSZ 16384
#define ZSZ   4864
#define AHI   4864
#define LASZ  23040
#define LBOFF (AHI + 2*LASZ)
#define LSMEM (LBOFF + 2*36864)
#define CASZ  41472
#define CBOFF (AHI + 2*CASZ)
#define CSMEM (CBOFF + 2*36864)

__device__ bf16  g_xeh[(size_t)NIMG*256*64], g_xel[(size_t)NIMG*256*64];
__device__ float g_xz[(size_t)2*NIMG*256*256];
__device__ bf16  g_h0h[2][(size_t)NIMG*256*64], g_h0l[2][(size_t)NIMG*256*64];
__device__ bf16  g_h1h[2][(size_t)NIMG*256*64], g_h1l[2][(size_t)NIMG*256*64];
__device__ bf16  g_sth[2][524288], g_stl[2][524288];
__device__ float g_cst[524288];
__device__ bf16  g_wh[(size_t)90*TAPSZ], g_wl[(size_t)90*TAPSZ];

__device__ __forceinline__ uint32_t smem_u32(const void* p) {
    uint32_t a;
    asm("{ .reg .u64 t; cvta.to.shared.u64 t, %1; cvt.u32.u64 %0, t; }" : "=r"(a) : "l"(p));
    return a;
}
__device__ __forceinline__ void ldsm4(uint32_t* r, uint32_t addr) {
    asm volatile("ldmatrix.sync.aligned.m8n8.x4.shared.b16 {%0,%1,%2,%3}, [%4];"
        : "=r"(r[0]), "=r"(r[1]), "=r"(r[2]), "=r"(r[3]) : "r"(addr));
}
__device__ __forceinline__ void mma16816(float* c, const uint32_t* a, const uint32_t* b) {
    asm volatile("mma.sync.aligned.m16n8k16.row.col.f32.bf16.bf16.f32 "
        "{%0,%1,%2,%3}, {%4,%5,%6,%7}, {%8,%9}, {%0,%1,%2,%3};"
        : "+f"(c[0]), "+f"(c[1]), "+f"(c[2]), "+f"(c[3])
        : "r"(a[0]), "r"(a[1]), "r"(a[2]), "r"(a[3]), "r"(b[0]), "r"(b[1]));
}
__device__ __forceinline__ void cpa16(uint32_t dst, const void* src) {
    asm volatile("cp.async.cg.shared.global [%0], [%1], 16;" :: "r"(dst), "l"(src) : "memory");
}
__device__ __forceinline__ void cp_commit() { asm volatile("cp.async.commit_group;" ::: "memory"); }
__device__ __forceinline__ void cp_wait1()  { asm volatile("cp.async.wait_group 1;" ::: "memory"); }
__device__ __forceinline__ void cp_wait0()  { asm volatile("cp.async.wait_group 0;" ::: "memory"); }
__device__ __forceinline__ float sigm(float x) { return __fdividef(1.f, 1.f + __expf(-x)); }

__device__ __forceinline__ void fill_A(char* sm, uint32_t asz,
        const bf16* hsrc, const bf16* lsrc, int r0, int nrows, int tid) {
    const uint4* hv = (const uint4*)hsrc;
    const uint4* lv = (const uint4*)lsrc;
    const uint4 z = make_uint4(0, 0, 0, 0);
    int tot = nrows * 16 * 8;
    for (int i = tid; i < tot; i += 256) {
        int ch = i & 7, p = i >> 3;
        int hr = p >> 4, c = p & 15;
        int row = r0 - 1 + hr;
        bool v = (row >= 0 && row < 16);
        int gi = (row * 16 + c) * 8 + ch;
        uint4 hval = v ? hv[gi] : z;
        uint4 lval = v ? lv[gi] : z;
        *(uint4*)(sm + AHI + p * 144 + ch * 16) = hval;
        *(uint4*)(sm + AHI + asz + p * 144 + ch * 16) = lval;
    }
}

__device__ __forceinline__ void prefB(char* sm, uint32_t boff, int st,
        const bf16* whi, const bf16* wlo, int ncol, int tid) {
    char* dh = sm + boff + st * 36864;
    const char* gh = (const char*)(whi + (size_t)ncol * 128 * 64);
    const char* gl = (const char*)(wlo + (size_t)ncol * 128 * 64);
    #pragma unroll
    for (int jj = 0; jj < 4; jj++) {
        int j = tid * 4 + jj;
        int row = j >> 3, of = (j & 7) * 16;
        uint32_t d = smem_u32(dh + row * 144 + of);
        cpa16(d,         gh + row * 128 + of);
        cpa16(d + 18432, gl + row * 128 + of);
    }
    cp_commit();
}

template<int MT>
__device__ __forceinline__ void mk_addrs(uint32_t smb, uint32_t asz, int warp_m,
        int warp_n, int l, uint32_t aH[][3], uint32_t aL[][3], uint32_t* bOf) {
    #pragma unroll
    for (int mt = 0; mt < MT; mt++) {
        int prow16 = warp_m * MT + mt;
        #pragma unroll
        for (int kw = 0; kw < 3; kw++) {
            int col = (l & 15) + kw - 1;
            uint32_t kpart = (uint32_t)(l >> 4) * 16;
            if ((unsigned)col > 15u) { aH[mt][kw] = smb + kpart; aL[mt][kw] = smb + kpart; }
            else {
                uint32_t base = smb + AHI + (uint32_t)(prow16 * 16 + col) * 144 + kpart;
                aH[mt][kw] = base;
                aL[mt][kw] = base + asz;
            }
        }
    }
    #pragma unroll
    for (int ntp = 0; ntp < 4; ntp++) {
        int nl = warp_n * 64 + ntp * 16 + (l & 7) + ((l >> 4) << 3);
        bOf[ntp] = (uint32_t)nl * 144 + ((l >> 3) & 1) * 16;
    }
}

template<int MT>
__device__ __forceinline__ void gemm_tap(float (*acc)[4],
        const uint32_t aH[][3], const uint32_t aL[][3], const uint32_t* bOf,
        uint32_t bbase, int kh, int kw) {
    uint32_t akk = (uint32_t)kh * 2304;
    #pragma unroll
    for (int kc = 0; kc < 4; kc++) {
        uint32_t ko = akk + (uint32_t)kc * 32;
        uint32_t ah[MT][4], al[MT][4], bh[4][4], bl[4][4];
        #pragma unroll
        for (int mt = 0; mt < MT; mt++) {
            ldsm4(ah[mt], aH[mt][kw] + ko);
            ldsm4(al[mt], aL[mt][kw] + ko);
        }
        #pragma unroll
        for (int ntp = 0; ntp < 4; ntp++) {
            ldsm4(bh[ntp], bbase + bOf[ntp] + (uint32_t)kc * 32);
            ldsm4(bl[ntp], bbase + 18432 + bOf[ntp] + (uint32_t)kc * 32);
        }
        #pragma unroll
        for (int mt = 0; mt < MT; mt++)
        #pragma unroll
        for (int ntp = 0; ntp < 4; ntp++) {
            float* c0 = acc[mt * 8 + 2 * ntp];
            float* c1 = acc[mt * 8 + 2 * ntp + 1];
            mma16816(c0, ah[mt], bh[ntp]);  mma16816(c1, ah[mt], bh[ntp] + 2);
            mma16816(c0, al[mt], bh[ntp]);  mma16816(c1, al[mt], bh[ntp] + 2);
            mma16816(c0, ah[mt], bl[ntp]);  mma16816(c1, ah[mt], bl[ntp] + 2);
        }
    }
}

__global__ void embed_kernel(const float* __restrict__ x) {
    int idx = blockIdx.x * 256 + threadIdx.x;
    if (idx >= NIMG * 256 * 64) return;
    int c = idx & 63, px = (idx >> 6) & 255, img = idx >> 14;
    int b = img / 28, t = img % 28;
    float v = 0.f;
    if (c < 24) {
        int flat = t * 24 + c;
        v = x[((size_t)(b * 112 + flat / 6) * 256 + px) * 6 + flat % 6];
    }
    bf16 h_ = __float2bfloat16(v);
    g_xeh[idx] = h_;
    g_xel[idx] = __float2bfloat16(v - __bfloat162float(h_));
}

__global__ void wprep_kernel(const float* __restrict__ w, bf16* __restrict__ hi,
                             bf16* __restrict__ lo, int IC, int ntap) {
    int idx = blockIdx.x * 256 + threadIdx.x;
    if (idx >= ntap * TAPSZ) return;
    int ic = idx & 63, n = (idx >> 6) & 255, tap = idx >> 14;
    int f = n >> 2, g = n & 3;
    int src = tap / 9, rtap = tap % 9, ics = src * 64 + ic;
    float v = (ics < IC) ? w[((size_t)rtap * IC + ics) * 256 + (g * 64 + f)] : 0.f;
    bf16 h_ = __float2bfloat16(v);
    hi[idx] = h_;
    lo[idx] = __float2bfloat16(v - __bfloat162float(h_));
}

__global__ void zero_states() {
    int idx = blockIdx.x * 256 + threadIdx.x;
    if (idx < 524288) {
        g_sth[0][idx] = __float2bfloat16(0.f);
        g_stl[0][idx] = __float2bfloat16(0.f);
        g_cst[idx] = 0.f;
    }
}

__global__ void __launch_bounds__(256, 1) conv_mma_kernel(
    const bf16* __restrict__ s0h, const bf16* __restrict__ s0l,
    const bf16* __restrict__ s1h, const bf16* __restrict__ s1l, int nsrc,
    const bf16* __restrict__ wfh, const bf16* __restrict__ wfl,
    const bf16* __restrict__ wbh, const bf16* __restrict__ wbl,
    const float* __restrict__ bf_, const float* __restrict__ bb_) {
    extern __shared__ char sm[];
    uint32_t smb = smem_u32(sm);
    int tid = threadIdx.x, l = tid & 31, w = tid >> 5;
    int warp_m = w >> 1, warp_n = w & 1, q = l & 3;
    int img = blockIdx.x, dir = blockIdx.y, ncol = blockIdx.z;
    const bf16* whi = dir ? wbh : wfh;
    const bf16* wlo = dir ? wbl : wfl;
    const float* bias = dir ? bb_ : bf_;

    for (int i = tid; i < ZSZ / 16; i += 256)
        *(uint4*)(sm + i * 16) = make_uint4(0, 0, 0, 0);
    fill_A(sm, CASZ, s0h + (size_t)img * 16384, s0l + (size_t)img * 16384, 0, 18, tid);

    uint32_t aH[4][3], aL[4][3], bOf[4];
    mk_addrs<4>(smb, CASZ, warp_m, warp_n, l, aH, aL, bOf);
    float acc[32][4];
    #pragma unroll
    for (int i = 0; i < 32; i++)
        acc[i][0] = acc[i][1] = acc[i][2] = acc[i][3] = 0.f;

    int T = nsrc * 9;
    prefB(sm, CBOFF, 0, whi, wlo, ncol, tid);
    __syncthreads();
    int st = 0;
    for (int tap = 0; tap < T; tap++) {
        if (tap + 1 < T) {
            prefB(sm, CBOFF, st ^ 1, whi + (size_t)(tap + 1) * TAPSZ,
                  wlo + (size_t)(tap + 1) * TAPSZ, ncol, tid);
            cp_wait1();
        } else cp_wait0();
        __syncthreads();
        if (tap == 9) {
            fill_A(sm, CASZ, s1h + (size_t)img * 16384, s1l + (size_t)img * 16384, 0, 18, tid);
            __syncthreads();
        }
        gemm_tap<4>(acc, aH, aL, bOf, smb + CBOFF + st * 36864, (tap % 9) / 3, (tap % 9) % 3);
        __syncthreads();
        st ^= 1;
    }

    size_t xzo = ((size_t)dir * NIMG + img) * 65536;
    #pragma unroll
    for (int mt = 0; mt < 4; mt++) {
        int m = warp_m * 64 + mt * 16 + (l >> 2);
        #pragma unroll
        for (int nt = 0; nt < 8; nt++) {
            float* c = acc[mt * 8 + nt];
            int n = ncol * 128 + warp_n * 64 + nt * 8 + q * 2;
            float b0 = __ldg(&bias[(n & 3) * 64 + (n >> 2)]);
            float b1 = __ldg(&bias[((n + 1) & 3) * 64 + ((n + 1) >> 2)]);
            *(float2*)(g_xz + xzo + (size_t)m * 256 + n) = make_float2(c[0] + b0, c[1] + b1);
            *(float2*)(g_xz + xzo + (size_t)(m + 8) * 256 + n) = make_float2(c[2] + b0, c[3] + b1);
        }
    }
}

__global__ void __launch_bounds__(256, 1) lstm_step_kernel(
    const bf16* __restrict__ wfh, const bf16* __restrict__ wfl,
    const bf16* __restrict__ wbh, const bf16* __restrict__ wbl,
    bf16* __restrict__ q0h, bf16* __restrict__ q0l,
    bf16* __restrict__ q1h, bf16* __restrict__ q1l, int s) {
    extern __shared__ char sm[];
    uint32_t smb = smem_u32(sm);
    int tid = threadIdx.x, l = tid & 31, w = tid >> 5;
    int warp_m = w >> 1, warp_n = w & 1, q = l & 3;
    int bx = blockIdx.x;
    int dir = bx >> 6, b = (bx >> 2) & 15, hf = (bx >> 1) & 1, ncol = bx & 1;
    int dirb = dir * 16 + b;
    int t = dir ? (27 - s) : s;
    int img = b * 28 + t;
    const bf16* whi = dir ? wbh : wfh;
    const bf16* wlo = dir ? wbl : wfl;

    for (int i = tid; i < ZSZ / 16; i += 256)
        *(uint4*)(sm + i * 16) = make_uint4(0, 0, 0, 0);
    fill_A(sm, LASZ, g_sth[s & 1] + (size_t)dirb * 16384,
           g_stl[s & 1] + (size_t)dirb * 16384, hf * 8, 10, tid);

    uint32_t aH[2][3], aL[2][3], bOf[4];
    mk_addrs<2>(smb, LASZ, warp_m, warp_n, l, aH, aL, bOf);
    float acc[16][4];
    #pragma unroll
    for (int i = 0; i < 16; i++)
        acc[i][0] = acc[i][1] = acc[i][2] = acc[i][3] = 0.f;

    prefB(sm, LBOFF, 0, whi, wlo, ncol, tid);
    __syncthreads();
    int st = 0;
    for (int tap = 0; tap < 9; tap++) {
        if (tap < 8) {
            prefB(sm, LBOFF, st ^ 1, whi + (size_t)(tap + 1) * TAPSZ,
                  wlo + (size_t)(tap + 1) * TAPSZ, ncol, tid);
            cp_wait1();
        } else cp_wait0();
        __syncthreads();
        gemm_tap<2>(acc, aH, aL, bOf, smb + LBOFF + st * 36864, tap / 3, tap % 3);
        __syncthreads();
        st ^= 1;
    }

    const float* xzb = g_xz + ((size_t)dir * NIMG + img) * 65536;
    size_t ctaBase = (size_t)bx * 4096;
    bool lower = !(l & 1);
    #pragma unroll
    for (int mt = 0; mt < 2; mt++) {
        int mbase = warp_m * 32 + mt * 16 + (l >> 2);
        #pragma unroll
        for (int nt = 0; nt < 8; nt++) {
            float* c = acc[mt * 8 + nt];
            float o0 = __shfl_xor_sync(0xffffffffu, c[0], 1);
            float o1 = __shfl_xor_sync(0xffffffffu, c[1], 1);
            float o2 = __shfl_xor_sync(0xffffffffu, c[2], 1);
            float o3 = __shfl_xor_sync(0xffffffffu, c[3], 1);
            float iv, fv, gv, ov;
            int m;
            if (lower) { iv = c[0]; fv = c[1]; gv = o0;  ov = o1;  m = mbase; }
            else       { iv = o2;  fv = o3;  gv = c[2]; ov = c[3]; m = mbase + 8; }
            int chp = q >> 1;
            int n4 = ncol * 128 + warp_n * 64 + nt * 8 + chp * 4;
            int pxg = hf * 128 + m;
            float4 z = *(const float4*)(xzb + (size_t)pxg * 256 + n4);
            iv = sigm(iv + z.x); fv = sigm(fv + z.y);
            gv = tanhf(gv + z.z); ov = sigm(ov + z.w);
            float* cs = g_cst + ctaBase + w * 512 + (mt * 8 + nt) * 32 + l;
            float cc = fv * (*cs) + iv * gv;
            *cs = cc;
            float hv = ov * tanhf(cc);
            bf16 hb = __float2bfloat16(hv);
            float lr = hv - __bfloat162float(hb);
            int chc = warp_n * 16 + nt * 2 + chp;
            *(bf16*)(sm + AHI + m * 64 + chc * 2) = hb;
            *(bf16*)(sm + AHI + 8192 + m * 64 + chc * 2) = __float2bfloat16(lr);
        }
    }
    __syncthreads();

    {
        int px = tid >> 1, part = tid & 1;
        const uint4* sh_ = (const uint4*)(sm + AHI + px * 64 + part * 32);
        const uint4* sl_ = (const uint4*)(sm + AHI + 8192 + px * 64 + part * 32);
        uint4 h0 = sh_[0], h1 = sh_[1];
        uint4 l0 = sl_[0], l1 = sl_[1];
        size_t sidx = (size_t)dirb * 16384 + (size_t)(hf * 128 + px) * 64 + ncol * 32 + part * 16;
        *(uint4*)(g_sth[(s + 1) & 1] + sidx) = h0;
        *(uint4*)(g_sth[(s + 1) & 1] + sidx + 8) = h1;
        *(uint4*)(g_stl[(s + 1) & 1] + sidx) = l0;
        *(uint4*)(g_stl[(s + 1) & 1] + sidx + 8) = l1;
        bf16* qh = dir ? q1h : q0h;
        bf16* ql = dir ? q1l : q0l;
        size_t qidx = ((size_t)img * 256 + hf * 128 + px) * 64 + ncol * 32 + part * 16;
        *(uint4*)(qh + qidx) = h0;
        *(uint4*)(qh + qidx + 8) = h1;
        *(uint4*)(ql + qidx) = l0;
        *(uint4*)(ql + qidx + 8) = l1;
    }
}

__global__ void __launch_bounds__(256) out_conv_kernel(
    const bf16* __restrict__ h1h0, const bf16* __restrict__ h1l0,
    const bf16* __restrict__ h1h1, const bf16* __restrict__ h1l1,
    const float* __restrict__ wout, const float* __restrict__ bout,
    float* __restrict__ out) {
    __shared__ float sh[3 * 16 * 128];
    __shared__ float ps[256];
    int n = blockIdx.x / 16, h = blockIdx.x % 16, tid = threadIdx.x;
    for (int i = tid; i < 3 * 16 * 128; i += 256) {
        int r = i / 2048, rem = i - r * 2048, c = rem >> 7, ch = rem & 127;
        int row = h - 1 + r;
        float v = 0.f;
        if (row >= 0 && row < 16) {
            size_t idx = ((size_t)n * 256 + row * 16 + c) * 64 + (ch & 63);
            if (ch < 64) v = __bfloat162float(h1h0[idx]) + __bfloat162float(h1l0[idx]);
            else         v = __bfloat162float(h1h1[idx]) + __bfloat162float(h1l1[idx]);
        }
        sh[i] = v;
    }
    __syncthreads();
    int p = tid >> 4, qq = tid & 15;
    float partial = 0.f;
    for (int kh = 0; kh < 3; kh++)
        for (int kw = 0; kw < 3; kw++) {
            int iw = p + kw - 1;
            if (iw < 0 || iw >= 16) continue;
            #pragma unroll
            for (int j = 0; j < 8; j++) {
                int ic = qq * 8 + j;
                partial += sh[(kh * 16 + iw) * 128 + ic] * wout[(kh * 3 + kw) * 128 + ic];
            }
        }
    ps[tid] = partial;
    __syncthreads();
    if (qq == 0) {
        float sum = bout[0];
        #pragma unroll
        for (int j = 0; j < 16; j++) sum += ps[p * 16 + j];
        out[((size_t)n * 16 + h) * 16 + p] = sum;
    }
}

extern "C" void kernel_launch(void* const* d_in, const int* in_sizes, int n_in,
                              void* d_out, int out_size) {
    const float* x    = (const float*)d_in[0];
    const float* wx0f = (const float*)d_in[1];
    const float* wh0f = (const float*)d_in[2];
    const float* b0f  = (const float*)d_in[3];
    const float* wx0b = (const float*)d_in[4];
    const float* wh0b = (const float*)d_in[5];
    const float* b0b  = (const float*)d_in[6];
    const float* wx1f = (const float*)d_in[7];
    const float* wh1f = (const float*)d_in[8];
    const float* b1f  = (const float*)d_in[9];
    const float* wx1b = (const float*)d_in[10];
    const float* wh1b = (const float*)d_in[11];
    const float* b1b  = (const float*)d_in[12];
    const float* wout = (const float*)d_in[13];
    const float* bout = (const float*)d_in[14];
    float* out = (float*)d_out;

    cudaFuncSetAttribute(conv_mma_kernel, cudaFuncAttributeMaxDynamicSharedMemorySize, CSMEM);
    cudaFuncSetAttribute(lstm_step_kernel, cudaFuncAttributeMaxDynamicSharedMemorySize, LSMEM);

    bf16 *wh, *wl, *xeh, *xel, *h0h0, *h0l0, *h1h0, *h1l0;
    cudaGetSymbolAddress((void**)&wh, g_wh);
    cudaGetSymbolAddress((void**)&wl, g_wl);
    cudaGetSymbolAddress((void**)&xeh, g_xeh);
    cudaGetSymbolAddress((void**)&xel, g_xel);
    cudaGetSymbolAddress((void**)&h0h0, g_h0h);
    cudaGetSymbolAddress((void**)&h0l0, g_h0l);
    cudaGetSymbolAddress((void**)&h1h0, g_h1h);
    cudaGetSymbolAddress((void**)&h1l0, g_h1l);
    const size_t HS = (size_t)NIMG * 256 * 64;
    bf16 *h0h1 = h0h0 + HS, *h0l1 = h0l0 + HS, *h1h1 = h1h0 + HS, *h1l1 = h1l0 + HS;

    wprep_kernel<<<(9*TAPSZ+255)/256, 256>>>(wx0f, wh + (size_t)0*TAPSZ,  wl + (size_t)0*TAPSZ,  24, 9);
    wprep_kernel<<<(9*TAPSZ+255)/256, 256>>>(wx0b, wh + (size_t)9*TAPSZ,  wl + (size_t)9*TAPSZ,  24, 9);
    wprep_kernel<<<(9*TAPSZ+255)/256, 256>>>(wh0f, wh + (size_t)18*TAPSZ, wl + (size_t)18*TAPSZ, 64, 9);
    wprep_kernel<<<(9*TAPSZ+255)/256, 256>>>(wh0b, wh + (size_t)27*TAPSZ, wl + (size_t)27*TAPSZ, 64, 9);
    wprep_kernel<<<(18*TAPSZ+255)/256, 256>>>(wx1f, wh + (size_t)36*TAPSZ, wl + (size_t)36*TAPSZ, 128, 18);
    wprep_kernel<<<(18*TAPSZ+255)/256, 256>>>(wx1b, wh + (size_t)54*TAPSZ, wl + (size_t)54*TAPSZ, 128, 18);
    wprep_kernel<<<(9*TAPSZ+255)/256, 256>>>(wh1f, wh + (size_t)72*TAPSZ, wl + (size_t)72*TAPSZ, 64, 9);
    wprep_kernel<<<(9*TAPSZ+255)/256, 256>>>(wh1b, wh + (size_t)81*TAPSZ, wl + (size_t)81*TAPSZ, 64, 9);
    embed_kernel<<<(NIMG*256*64+255)/256, 256>>>(x);

    dim3 cgrid(NIMG, 2, 2);
    conv_mma_kernel<<<cgrid, 256, CSMEM>>>(xeh, xel, xeh, xel, 1,
        wh + (size_t)0*TAPSZ, wl + (size_t)0*TAPSZ, wh + (size_t)9*TAPSZ, wl + (size_t)9*TAPSZ, b0f, b0b);
    zero_states<<<(524288+255)/256, 256>>>();
    for (int s = 0; s < 28; s++)
        lstm_step_kernel<<<128, 256, LSMEM>>>(
            wh + (size_t)18*TAPSZ, wl + (size_t)18*TAPSZ, wh + (size_t)27*TAPSZ, wl + (size_t)27*TAPSZ,
            h0h0, h0l0, h0h1, h0l1, s);
    conv_mma_kernel<<<cgrid, 256, CSMEM>>>(h0h0, h0l0, h0h1, h0l1, 2,
        wh + (size_t)36*TAPSZ, wl + (size_t)36*TAPSZ, wh + (size_t)54*TAPSZ, wl + (size_t)54*TAPSZ, b1f, b1b);
    zero_states<<<(524288+255)/256, 256>>>();
    for (int s = 0; s < 28; s++)
        lstm_step_kernel<<<128, 256, LSMEM>>>(
            wh + (size_t)72*TAPSZ, wl + (size_t)72*TAPSZ, wh + (size_t)81*TAPSZ, wl + (size_t)81*TAPSZ,
            h1h0, h1l0, h1h1, h1l1, s);

    out_conv_kernel<<<NIMG*16, 256>>>(h1h0, h1l0, h1h1, h1l1, wout, bout, out);
}

// round 6
// speedup vs baseline: 4.3785x; 1.5184x over previous
#include <cuda_runtime.h>
#include <cuda_fp16.h>
#include <stdint.h>
#include <math.h>

typedef __half fp16;

#define NIMG 448
#define TAPSZ 16384            // elements per tap (256 oc x 64 ic)
#define ZSZ   4864
#define AHI   4864
// LSTM: A 160px x 144B hi+lo, B 9 taps x 18432
#define LASZ  23040
#define LBOFF (AHI + 2*LASZ)           // 50944
#define LSMEM (LBOFF + 9*18432)        // 216832
// conv: A 288px x 144B hi+lo, B ring 4 x 18432
#define CASZ  41472
#define CBOFF (AHI + 2*CASZ)           // 87808
#define CSMEM (CBOFF + 4*18432)        // 161536

__device__ fp16  g_xeh[(size_t)NIMG*256*64], g_xel[(size_t)NIMG*256*64];
__device__ float g_xz[(size_t)2*NIMG*256*256];
__device__ fp16  g_h0h[2][(size_t)NIMG*256*64], g_h0l[2][(size_t)NIMG*256*64];
__device__ fp16  g_h1h[2][(size_t)NIMG*256*64], g_h1l[2][(size_t)NIMG*256*64];
__device__ fp16  g_sth[2][524288], g_stl[2][524288];
__device__ float g_cst[524288];
__device__ fp16  g_w[(size_t)90*TAPSZ];

__device__ __forceinline__ uint32_t smem_u32(const void* p) {
    uint32_t a;
    asm("{ .reg .u64 t; cvta.to.shared.u64 t, %1; cvt.u32.u64 %0, t; }" : "=r"(a) : "l"(p));
    return a;
}
__device__ __forceinline__ void ldsm4(uint32_t* r, uint32_t addr) {
    asm volatile("ldmatrix.sync.aligned.m8n8.x4.shared.b16 {%0,%1,%2,%3}, [%4];"
        : "=r"(r[0]), "=r"(r[1]), "=r"(r[2]), "=r"(r[3]) : "r"(addr));
}
__device__ __forceinline__ void mma16816(float* c, const uint32_t* a, const uint32_t* b) {
    asm volatile("mma.sync.aligned.m16n8k16.row.col.f32.f16.f16.f32 "
        "{%0,%1,%2,%3}, {%4,%5,%6,%7}, {%8,%9}, {%0,%1,%2,%3};"
        : "+f"(c[0]), "+f"(c[1]), "+f"(c[2]), "+f"(c[3])
        : "r"(a[0]), "r"(a[1]), "r"(a[2]), "r"(a[3]), "r"(b[0]), "r"(b[1]));
}
__device__ __forceinline__ void cpa16(uint32_t dst, const void* src) {
    asm volatile("cp.async.cg.shared.global [%0], [%1], 16;" :: "r"(dst), "l"(src) : "memory");
}
__device__ __forceinline__ void cp_commit() { asm volatile("cp.async.commit_group;" ::: "memory"); }
__device__ __forceinline__ void cp_wait2()  { asm volatile("cp.async.wait_group 2;" ::: "memory"); }
__device__ __forceinline__ void cp_wait1()  { asm volatile("cp.async.wait_group 1;" ::: "memory"); }
__device__ __forceinline__ void cp_wait0()  { asm volatile("cp.async.wait_group 0;" ::: "memory"); }
__device__ __forceinline__ float sigm(float x) { return __fdividef(1.f, 1.f + __expf(-x)); }

__device__ __forceinline__ void fill_A(char* sm, uint32_t asz,
        const fp16* hsrc, const fp16* lsrc, int r0, int nrows, int tid) {
    const uint4* hv = (const uint4*)hsrc;
    const uint4* lv = (const uint4*)lsrc;
    const uint4 z = make_uint4(0, 0, 0, 0);
    int tot = nrows * 16 * 8;
    for (int i = tid; i < tot; i += 256) {
        int ch = i & 7, p = i >> 3;
        int hr = p >> 4, c = p & 15;
        int row = r0 - 1 + hr;
        bool v = (row >= 0 && row < 16);
        int gi = (row * 16 + c) * 8 + ch;
        uint4 hval = v ? hv[gi] : z;
        uint4 lval = v ? lv[gi] : z;
        *(uint4*)(sm + AHI + p * 144 + ch * 16) = hval;
        *(uint4*)(sm + AHI + asz + p * 144 + ch * 16) = lval;
    }
}

// one tap of B (128 oc rows x 128B) into ring slot
__device__ __forceinline__ void prefB(char* sm, int slot, const fp16* w,
                                      int tap, int ncol, int tid) {
    char* dh = sm + CBOFF + slot * 18432;
    const char* g = (const char*)w + (size_t)tap * 32768 + (size_t)ncol * 16384;
    #pragma unroll
    for (int jj = 0; jj < 4; jj++) {
        int j = tid * 4 + jj;
        int row = j >> 3, of = (j & 7) * 16;
        cpa16(smem_u32(dh + row * 144 + of), g + row * 128 + of);
    }
    cp_commit();
}

// all 9 taps at once (LSTM)
__device__ __forceinline__ void prefB_all(char* sm, const fp16* w, int ncol, int tid) {
    const char* g = (const char*)w + (size_t)ncol * 16384;
    for (int i = tid; i < 9216; i += 256) {
        int tap = i >> 10, j = i & 1023;
        int row = j >> 3, of = (j & 7) * 16;
        cpa16(smem_u32(sm + LBOFF + tap * 18432 + row * 144 + of),
              g + (size_t)tap * 32768 + row * 128 + of);
    }
    cp_commit();
}

template<int MT>
__device__ __forceinline__ void mk_addrs(uint32_t smb, uint32_t asz, int warp_m,
        int warp_n, int l, uint32_t aH[][3], uint32_t aL[][3], uint32_t* bOf) {
    #pragma unroll
    for (int mt = 0; mt < MT; mt++) {
        int prow16 = warp_m * MT + mt;
        #pragma unroll
        for (int kw = 0; kw < 3; kw++) {
            int col = (l & 15) + kw - 1;
            uint32_t kpart = (uint32_t)(l >> 4) * 16;
            if ((unsigned)col > 15u) { aH[mt][kw] = smb + kpart; aL[mt][kw] = smb + kpart; }
            else {
                uint32_t base = smb + AHI + (uint32_t)(prow16 * 16 + col) * 144 + kpart;
                aH[mt][kw] = base;
                aL[mt][kw] = base + asz;
            }
        }
    }
    #pragma unroll
    for (int ntp = 0; ntp < 4; ntp++) {
        int nl = warp_n * 64 + ntp * 16 + (l & 7) + ((l >> 4) << 3);
        bOf[ntp] = (uint32_t)nl * 144 + ((l >> 3) & 1) * 16;
    }
}

// 2-term tap: (Ahi + Alo) * B, K=64
template<int MT>
__device__ __forceinline__ void gemm_tap2(float (*acc)[4],
        const uint32_t aH[][3], const uint32_t aL[][3], const uint32_t* bOf,
        uint32_t bbase, int kh, int kw) {
    uint32_t akk = (uint32_t)kh * 2304;
    #pragma unroll
    for (int kc = 0; kc < 4; kc++) {
        uint32_t ko = akk + (uint32_t)kc * 32;
        uint32_t ah[MT][4], al[MT][4], bh[4][4];
        #pragma unroll
        for (int mt = 0; mt < MT; mt++) {
            ldsm4(ah[mt], aH[mt][kw] + ko);
            ldsm4(al[mt], aL[mt][kw] + ko);
        }
        #pragma unroll
        for (int ntp = 0; ntp < 4; ntp++)
            ldsm4(bh[ntp], bbase + bOf[ntp] + (uint32_t)kc * 32);
        #pragma unroll
        for (int mt = 0; mt < MT; mt++)
        #pragma unroll
        for (int ntp = 0; ntp < 4; ntp++) {
            float* c0 = acc[mt * 8 + 2 * ntp];
            float* c1 = acc[mt * 8 + 2 * ntp + 1];
            mma16816(c0, ah[mt], bh[ntp]);  mma16816(c1, ah[mt], bh[ntp] + 2);
            mma16816(c0, al[mt], bh[ntp]);  mma16816(c1, al[mt], bh[ntp] + 2);
        }
    }
}

__global__ void embed_kernel(const float* __restrict__ x) {
    int idx = blockIdx.x * 256 + threadIdx.x;
    if (idx >= NIMG * 256 * 64) return;
    int c = idx & 63, px = (idx >> 6) & 255, img = idx >> 14;
    int b = img / 28, t = img % 28;
    float v = 0.f;
    if (c < 24) {
        int flat = t * 24 + c;
        v = x[((size_t)(b * 112 + flat / 6) * 256 + px) * 6 + flat % 6];
    }
    fp16 h_ = __float2half(v);
    g_xeh[idx] = h_;
    g_xel[idx] = __float2half(v - __half2float(h_));
}

__global__ void wprep_kernel(const float* __restrict__ w, fp16* __restrict__ o,
                             int IC, int ntap) {
    int idx = blockIdx.x * 256 + threadIdx.x;
    if (idx >= ntap * TAPSZ) return;
    int ic = idx & 63, n = (idx >> 6) & 255, tap = idx >> 14;
    int f = n >> 2, g = n & 3;
    int src = tap / 9, rtap = tap % 9, ics = src * 64 + ic;
    float v = (ics < IC) ? w[((size_t)rtap * IC + ics) * 256 + (g * 64 + f)] : 0.f;
    o[idx] = __float2half(v);
}

__global__ void zero_states() {
    int idx = blockIdx.x * 256 + threadIdx.x;
    if (idx < 524288) {
        g_sth[0][idx] = __float2half(0.f);
        g_stl[0][idx] = __float2half(0.f);
        g_cst[idx] = 0.f;
    }
}

template<int NSRC>
__global__ void __launch_bounds__(256, 1) conv_mma_kernel(
    const fp16* __restrict__ s0h, const fp16* __restrict__ s0l,
    const fp16* __restrict__ s1h, const fp16* __restrict__ s1l,
    const fp16* __restrict__ wf, const fp16* __restrict__ wb,
    const float* __restrict__ bf_, const float* __restrict__ bb_) {
    extern __shared__ char sm[];
    uint32_t smb = smem_u32(sm);
    int tid = threadIdx.x, l = tid & 31, w = tid >> 5;
    int warp_m = w >> 1, warp_n = w & 1, q = l & 3;
    int img = blockIdx.x, dir = blockIdx.y, ncol = blockIdx.z;
    const fp16* wsel = dir ? wb : wf;
    const float* bias = dir ? bb_ : bf_;
    const int T = NSRC * 9;

    for (int i = tid; i < ZSZ / 16; i += 256)
        *(uint4*)(sm + i * 16) = make_uint4(0, 0, 0, 0);
    fill_A(sm, CASZ, s0h + (size_t)img * 16384, s0l + (size_t)img * 16384, 0, 18, tid);
    prefB(sm, 0, wsel, 0, ncol, tid);
    prefB(sm, 1, wsel, 1, ncol, tid);
    prefB(sm, 2, wsel, 2, ncol, tid);

    uint32_t aH[4][3], aL[4][3], bOf[4];
    mk_addrs<4>(smb, CASZ, warp_m, warp_n, l, aH, aL, bOf);
    float acc[32][4];
    #pragma unroll
    for (int i = 0; i < 32; i++)
        acc[i][0] = acc[i][1] = acc[i][2] = acc[i][3] = 0.f;

    #pragma unroll
    for (int tap = 0; tap < T; tap++) {
        if (tap < T - 2) cp_wait2(); else if (tap == T - 2) cp_wait1(); else cp_wait0();
        __syncthreads();
        if (NSRC == 2 && tap == 9) {
            fill_A(sm, CASZ, s1h + (size_t)img * 16384, s1l + (size_t)img * 16384, 0, 18, tid);
            __syncthreads();
        }
        gemm_tap2<4>(acc, aH, aL, bOf, smb + CBOFF + (tap & 3) * 18432,
                     (tap % 9) / 3, (tap % 9) % 3);
        __syncthreads();
        if (tap + 3 < T) prefB(sm, (tap + 3) & 3, wsel, tap + 3, ncol, tid);
    }

    size_t xzo = ((size_t)dir * NIMG + img) * 65536;
    #pragma unroll
    for (int mt = 0; mt < 4; mt++) {
        int m = warp_m * 64 + mt * 16 + (l >> 2);
        #pragma unroll
        for (int nt = 0; nt < 8; nt++) {
            float* c = acc[mt * 8 + nt];
            int n = ncol * 128 + warp_n * 64 + nt * 8 + q * 2;
            float b0 = __ldg(&bias[(n & 3) * 64 + (n >> 2)]);
            float b1 = __ldg(&bias[((n + 1) & 3) * 64 + ((n + 1) >> 2)]);
            *(float2*)(g_xz + xzo + (size_t)m * 256 + n) = make_float2(c[0] + b0, c[1] + b1);
            *(float2*)(g_xz + xzo + (size_t)(m + 8) * 256 + n) = make_float2(c[2] + b0, c[3] + b1);
        }
    }
}

__global__ void __launch_bounds__(256, 1) lstm_step_kernel(
    const fp16* __restrict__ wf, const fp16* __restrict__ wb,
    fp16* __restrict__ q0h, fp16* __restrict__ q0l,
    fp16* __restrict__ q1h, fp16* __restrict__ q1l, int s) {
    extern __shared__ char sm[];
    uint32_t smb = smem_u32(sm);
    int tid = threadIdx.x, l = tid & 31, w = tid >> 5;
    int warp_m = w >> 1, warp_n = w & 1, q = l & 3;
    int bx = blockIdx.x;
    int dir = bx >> 6, b = (bx >> 2) & 15, hf = (bx >> 1) & 1, ncol = bx & 1;
    int dirb = dir * 16 + b;
    int t = dir ? (27 - s) : s;
    int img = b * 28 + t;
    const fp16* wsel = dir ? wb : wf;

    prefB_all(sm, wsel, ncol, tid);
    for (int i = tid; i < ZSZ / 16; i += 256)
        *(uint4*)(sm + i * 16) = make_uint4(0, 0, 0, 0);
    fill_A(sm, LASZ, g_sth[s & 1] + (size_t)dirb * 16384,
           g_stl[s & 1] + (size_t)dirb * 16384, hf * 8, 10, tid);

    uint32_t aH[2][3], aL[2][3], bOf[4];
    mk_addrs<2>(smb, LASZ, warp_m, warp_n, l, aH, aL, bOf);
    float acc[16][4];
    #pragma unroll
    for (int i = 0; i < 16; i++)
        acc[i][0] = acc[i][1] = acc[i][2] = acc[i][3] = 0.f;

    cp_wait0();
    __syncthreads();
    #pragma unroll
    for (int t9 = 0; t9 < 9; t9++)
        gemm_tap2<2>(acc, aH, aL, bOf, smb + LBOFF + t9 * 18432, t9 / 3, t9 % 3);
    __syncthreads();   // all warps done reading A before staging overwrites it

    const float* xzb = g_xz + ((size_t)dir * NIMG + img) * 65536;
    size_t ctaBase = (size_t)bx * 4096;
    bool lower = !(l & 1);
    #pragma unroll
    for (int mt = 0; mt < 2; mt++) {
        int mbase = warp_m * 32 + mt * 16 + (l >> 2);
        #pragma unroll
        for (int nt = 0; nt < 8; nt++) {
            float* c = acc[mt * 8 + nt];
            float o0 = __shfl_xor_sync(0xffffffffu, c[0], 1);
            float o1 = __shfl_xor_sync(0xffffffffu, c[1], 1);
            float o2 = __shfl_xor_sync(0xffffffffu, c[2], 1);
            float o3 = __shfl_xor_sync(0xffffffffu, c[3], 1);
            float iv, fv, gv, ov;
            int m;
            if (lower) { iv = c[0]; fv = c[1]; gv = o0;  ov = o1;  m = mbase; }
            else       { iv = o2;  fv = o3;  gv = c[2]; ov = c[3]; m = mbase + 8; }
            int chp = q >> 1;
            int n4 = ncol * 128 + warp_n * 64 + nt * 8 + chp * 4;
            int pxg = hf * 128 + m;
            float4 z = *(const float4*)(xzb + (size_t)pxg * 256 + n4);
            iv = sigm(iv + z.x); fv = sigm(fv + z.y);
            gv = tanhf(gv + z.z); ov = sigm(ov + z.w);
            float* cs = g_cst + ctaBase + w * 512 + (mt * 8 + nt) * 32 + l;
            float cc = fv * (*cs) + iv * gv;
            *cs = cc;
            float hv = ov * tanhf(cc);
            fp16 hb = __float2half(hv);
            float lr = hv - __half2float(hb);
            int chc = warp_n * 16 + nt * 2 + chp;
            *(fp16*)(sm + AHI + m * 64 + chc * 2) = hb;
            *(fp16*)(sm + AHI + 8192 + m * 64 + chc * 2) = __float2half(lr);
        }
    }
    __syncthreads();

    {
        int px = tid >> 1, part = tid & 1;
        const uint4* sh_ = (const uint4*)(sm + AHI + px * 64 + part * 32);
        const uint4* sl_ = (const uint4*)(sm + AHI + 8192 + px * 64 + part * 32);
        uint4 h0 = sh_[0], h1 = sh_[1];
        uint4 l0 = sl_[0], l1 = sl_[1];
        size_t sidx = (size_t)dirb * 16384 + (size_t)(hf * 128 + px) * 64 + ncol * 32 + part * 16;
        *(uint4*)(g_sth[(s + 1) & 1] + sidx) = h0;
        *(uint4*)(g_sth[(s + 1) & 1] + sidx + 8) = h1;
        *(uint4*)(g_stl[(s + 1) & 1] + sidx) = l0;
        *(uint4*)(g_stl[(s + 1) & 1] + sidx + 8) = l1;
        fp16* qh = dir ? q1h : q0h;
        fp16* ql = dir ? q1l : q0l;
        size_t qidx = ((size_t)img * 256 + hf * 128 + px) * 64 + ncol * 32 + part * 16;
        *(uint4*)(qh + qidx) = h0;
        *(uint4*)(qh + qidx + 8) = h1;
        *(uint4*)(ql + qidx) = l0;
        *(uint4*)(ql + qidx + 8) = l1;
    }
}

__global__ void __launch_bounds__(256) out_conv_kernel(
    const fp16* __restrict__ h1h0, const fp16* __restrict__ h1l0,
    const fp16* __restrict__ h1h1, const fp16* __restrict__ h1l1,
    const float* __restrict__ wout, const float* __restrict__ bout,
    float* __restrict__ out) {
    __shared__ float sh[3 * 16 * 128];
    __shared__ float ps[256];
    int n = blockIdx.x / 16, h = blockIdx.x % 16, tid = threadIdx.x;
    for (int i = tid; i < 3 * 16 * 128; i += 256) {
        int r = i / 2048, rem = i - r * 2048, c = rem >> 7, ch = rem & 127;
        int row = h - 1 + r;
        float v = 0.f;
        if (row >= 0 && row < 16) {
            size_t idx = ((size_t)n * 256 + row * 16 + c) * 64 + (ch & 63);
            if (ch < 64) v = __half2float(h1h0[idx]) + __half2float(h1l0[idx]);
            else         v = __half2float(h1h1[idx]) + __half2float(h1l1[idx]);
        }
        sh[i] = v;
    }
    __syncthreads();
    int p = tid >> 4, qq = tid & 15;
    float partial = 0.f;
    for (int kh = 0; kh < 3; kh++)
        for (int kw = 0; kw < 3; kw++) {
            int iw = p + kw - 1;
            if (iw < 0 || iw >= 16) continue;
            #pragma unroll
            for (int j = 0; j < 8; j++) {
                int ic = qq * 8 + j;
                partial += sh[(kh * 16 + iw) * 128 + ic] * wout[(kh * 3 + kw) * 128 + ic];
            }
        }
    ps[tid] = partial;
    __syncthreads();
    if (qq == 0) {
        float sum = bout[0];
        #pragma unroll
        for (int j = 0; j < 16; j++) sum += ps[p * 16 + j];
        out[((size_t)n * 16 + h) * 16 + p] = sum;
    }
}

extern "C" void kernel_launch(void* const* d_in, const int* in_sizes, int n_in,
                              void* d_out, int out_size) {
    const float* x    = (const float*)d_in[0];
    const float* wx0f = (const float*)d_in[1];
    const float* wh0f = (const float*)d_in[2];
    const float* b0f  = (const float*)d_in[3];
    const float* wx0b = (const float*)d_in[4];
    const float* wh0b = (const float*)d_in[5];
    const float* b0b  = (const float*)d_in[6];
    const float* wx1f = (const float*)d_in[7];
    const float* wh1f = (const float*)d_in[8];
    const float* b1f  = (const float*)d_in[9];
    const float* wx1b = (const float*)d_in[10];
    const float* wh1b = (const float*)d_in[11];
    const float* b1b  = (const float*)d_in[12];
    const float* wout = (const float*)d_in[13];
    const float* bout = (const float*)d_in[14];
    float* out = (float*)d_out;

    cudaFuncSetAttribute(conv_mma_kernel<1>, cudaFuncAttributeMaxDynamicSharedMemorySize, CSMEM);
    cudaFuncSetAttribute(conv_mma_kernel<2>, cudaFuncAttributeMaxDynamicSharedMemorySize, CSMEM);
    cudaFuncSetAttribute(lstm_step_kernel, cudaFuncAttributeMaxDynamicSharedMemorySize, LSMEM);

    fp16 *wg, *xeh, *xel, *h0h0, *h0l0, *h1h0, *h1l0;
    cudaGetSymbolAddress((void**)&wg, g_w);
    cudaGetSymbolAddress((void**)&xeh, g_xeh);
    cudaGetSymbolAddress((void**)&xel, g_xel);
    cudaGetSymbolAddress((void**)&h0h0, g_h0h);
    cudaGetSymbolAddress((void**)&h0l0, g_h0l);
    cudaGetSymbolAddress((void**)&h1h0, g_h1h);
    cudaGetSymbolAddress((void**)&h1l0, g_h1l);
    const size_t HS = (size_t)NIMG * 256 * 64;
    fp16 *h0h1 = h0h0 + HS, *h0l1 = h0l0 + HS, *h1h1 = h1h0 + HS, *h1l1 = h1l0 + HS;

    wprep_kernel<<<(9*TAPSZ+255)/256, 256>>>(wx0f, wg + (size_t)0*TAPSZ,  24, 9);
    wprep_kernel<<<(9*TAPSZ+255)/256, 256>>>(wx0b, wg + (size_t)9*TAPSZ,  24, 9);
    wprep_kernel<<<(9*TAPSZ+255)/256, 256>>>(wh0f, wg + (size_t)18*TAPSZ, 64, 9);
    wprep_kernel<<<(9*TAPSZ+255)/256, 256>>>(wh0b, wg + (size_t)27*TAPSZ, 64, 9);
    wprep_kernel<<<(18*TAPSZ+255)/256, 256>>>(wx1f, wg + (size_t)36*TAPSZ, 128, 18);
    wprep_kernel<<<(18*TAPSZ+255)/256, 256>>>(wx1b, wg + (size_t)54*TAPSZ, 128, 18);
    wprep_kernel<<<(9*TAPSZ+255)/256, 256>>>(wh1f, wg + (size_t)72*TAPSZ, 64, 9);
    wprep_kernel<<<(9*TAPSZ+255)/256, 256>>>(wh1b, wg + (size_t)81*TAPSZ, 64, 9);
    embed_kernel<<<(NIMG*256*64+255)/256, 256>>>(x);

    dim3 cgrid(NIMG, 2, 2);
    conv_mma_kernel<1><<<cgrid, 256, CSMEM>>>(xeh, xel, xeh, xel,
        wg + (size_t)0*TAPSZ, wg + (size_t)9*TAPSZ, b0f, b0b);
    zero_states<<<(524288+255)/256, 256>>>();
    for (int s = 0; s < 28; s++)
        lstm_step_kernel<<<128, 256, LSMEM>>>(
            wg + (size_t)18*TAPSZ, wg + (size_t)27*TAPSZ, h0h0, h0l0, h0h1, h0l1, s);
    conv_mma_kernel<2><<<cgrid, 256, CSMEM>>>(h0h0, h0l0, h0h1, h0l1,
        wg + (size_t)36*TAPSZ, wg + (size_t)54*TAPSZ, b1f, b1b);
    zero_states<<<(524288+255)/256, 256>>>();
    for (int s = 0; s < 28; s++)
        lstm_step_kernel<<<128, 256, LSMEM>>>(
            wg + (size_t)72*TAPSZ, wg + (size_t)81*TAPSZ, h1h0, h1l0, h1h1, h1l1, s);

    out_conv_kernel<<<NIMG*16, 256>>>(h1h0, h1l0, h1h1, h1l1, wout, bout, out);
}

// round 7
// speedup vs baseline: 4.5673x; 1.0431x over previous
#include <cuda_runtime.h>
#include <cuda_fp16.h>
#include <stdint.h>
#include <math.h>

typedef __half fp16;

#define NIMG 448
#define TAPSZ 16384            // elements per tap (256 oc x 64 ic)
#define ZSZ   4864
#define AHI   4864
// LSTM: A 160px x 144B hi+lo, B 9 taps x 18432
#define LASZ  23040
#define LBOFF (AHI + 2*LASZ)           // 50944
#define LSMEM (LBOFF + 9*18432)        // 216832
// conv: A 288px x 144B hi+lo, B ring 4 x 18432
#define CASZ  41472
#define CBOFF (AHI + 2*CASZ)           // 87808
#define CSMEM (CBOFF + 4*18432)        // 161536

__device__ fp16  g_xeh[(size_t)NIMG*256*64], g_xel[(size_t)NIMG*256*64];
__device__ float g_xz[(size_t)2*NIMG*256*256];
__device__ fp16  g_h0h[2][(size_t)NIMG*256*64], g_h0l[2][(size_t)NIMG*256*64];
__device__ fp16  g_h1h[2][(size_t)NIMG*256*64], g_h1l[2][(size_t)NIMG*256*64];
__device__ fp16  g_sth[2][524288], g_stl[2][524288];
__device__ float g_cst[524288];
__device__ fp16  g_w[(size_t)90*TAPSZ];
__device__ unsigned g_barcnt;

__device__ __forceinline__ uint32_t smem_u32(const void* p) {
    uint32_t a;
    asm("{ .reg .u64 t; cvta.to.shared.u64 t, %1; cvt.u32.u64 %0, t; }" : "=r"(a) : "l"(p));
    return a;
}
__device__ __forceinline__ void ldsm4(uint32_t* r, uint32_t addr) {
    asm volatile("ldmatrix.sync.aligned.m8n8.x4.shared.b16 {%0,%1,%2,%3}, [%4];"
        : "=r"(r[0]), "=r"(r[1]), "=r"(r[2]), "=r"(r[3]) : "r"(addr));
}
__device__ __forceinline__ void mma16816(float* c, const uint32_t* a, const uint32_t* b) {
    asm volatile("mma.sync.aligned.m16n8k16.row.col.f32.f16.f16.f32 "
        "{%0,%1,%2,%3}, {%4,%5,%6,%7}, {%8,%9}, {%0,%1,%2,%3};"
        : "+f"(c[0]), "+f"(c[1]), "+f"(c[2]), "+f"(c[3])
        : "r"(a[0]), "r"(a[1]), "r"(a[2]), "r"(a[3]), "r"(b[0]), "r"(b[1]));
}
__device__ __forceinline__ void cpa16(uint32_t dst, const void* src) {
    asm volatile("cp.async.cg.shared.global [%0], [%1], 16;" :: "r"(dst), "l"(src) : "memory");
}
__device__ __forceinline__ void cp_commit() { asm volatile("cp.async.commit_group;" ::: "memory"); }
__device__ __forceinline__ void cp_wait2()  { asm volatile("cp.async.wait_group 2;" ::: "memory"); }
__device__ __forceinline__ void cp_wait1()  { asm volatile("cp.async.wait_group 1;" ::: "memory"); }
__device__ __forceinline__ void cp_wait0()  { asm volatile("cp.async.wait_group 0;" ::: "memory"); }
__device__ __forceinline__ float sigm(float x) { return __fdividef(1.f, 1.f + __expf(-x)); }

__device__ __forceinline__ void fill_A(char* sm, uint32_t asz,
        const fp16* hsrc, const fp16* lsrc, int r0, int nrows, int tid) {
    const uint4* hv = (const uint4*)hsrc;
    const uint4* lv = (const uint4*)lsrc;
    const uint4 z = make_uint4(0, 0, 0, 0);
    int tot = nrows * 16 * 8;
    for (int i = tid; i < tot; i += 256) {
        int ch = i & 7, p = i >> 3;
        int hr = p >> 4, c = p & 15;
        int row = r0 - 1 + hr;
        bool v = (row >= 0 && row < 16);
        int gi = (row * 16 + c) * 8 + ch;
        uint4 hval = v ? hv[gi] : z;
        uint4 lval = v ? lv[gi] : z;
        *(uint4*)(sm + AHI + p * 144 + ch * 16) = hval;
        *(uint4*)(sm + AHI + asz + p * 144 + ch * 16) = lval;
    }
}

__device__ __forceinline__ void prefB(char* sm, int slot, const fp16* w,
                                      int tap, int ncol, int tid) {
    char* dh = sm + CBOFF + slot * 18432;
    const char* g = (const char*)w + (size_t)tap * 32768 + (size_t)ncol * 16384;
    #pragma unroll
    for (int jj = 0; jj < 4; jj++) {
        int j = tid * 4 + jj;
        int row = j >> 3, of = (j & 7) * 16;
        cpa16(smem_u32(dh + row * 144 + of), g + row * 128 + of);
    }
    cp_commit();
}

__device__ __forceinline__ void prefB_all(char* sm, const fp16* w, int ncol, int tid) {
    const char* g = (const char*)w + (size_t)ncol * 16384;
    for (int i = tid; i < 9216; i += 256) {
        int tap = i >> 10, j = i & 1023;
        int row = j >> 3, of = (j & 7) * 16;
        cpa16(smem_u32(sm + LBOFF + tap * 18432 + row * 144 + of),
              g + (size_t)tap * 32768 + row * 128 + of);
    }
    cp_commit();
}

template<int MT>
__device__ __forceinline__ void mk_addrs(uint32_t smb, uint32_t asz, int warp_m,
        int warp_n, int l, uint32_t aH[][3], uint32_t aL[][3], uint32_t* bOf) {
    #pragma unroll
    for (int mt = 0; mt < MT; mt++) {
        int prow16 = warp_m * MT + mt;
        #pragma unroll
        for (int kw = 0; kw < 3; kw++) {
            int col = (l & 15) + kw - 1;
            uint32_t kpart = (uint32_t)(l >> 4) * 16;
            if ((unsigned)col > 15u) { aH[mt][kw] = smb + kpart; aL[mt][kw] = smb + kpart; }
            else {
                uint32_t base = smb + AHI + (uint32_t)(prow16 * 16 + col) * 144 + kpart;
                aH[mt][kw] = base;
                aL[mt][kw] = base + asz;
            }
        }
    }
    #pragma unroll
    for (int ntp = 0; ntp < 4; ntp++) {
        int nl = warp_n * 64 + ntp * 16 + (l & 7) + ((l >> 4) << 3);
        bOf[ntp] = (uint32_t)nl * 144 + ((l >> 3) & 1) * 16;
    }
}

template<int MT>
__device__ __forceinline__ void gemm_tap2(float (*acc)[4],
        const uint32_t aH[][3], const uint32_t aL[][3], const uint32_t* bOf,
        uint32_t bbase, int kh, int kw) {
    uint32_t akk = (uint32_t)kh * 2304;
    #pragma unroll
    for (int kc = 0; kc < 4; kc++) {
        uint32_t ko = akk + (uint32_t)kc * 32;
        uint32_t ah[MT][4], al[MT][4], bh[4][4];
        #pragma unroll
        for (int mt = 0; mt < MT; mt++) {
            ldsm4(ah[mt], aH[mt][kw] + ko);
            ldsm4(al[mt], aL[mt][kw] + ko);
        }
        #pragma unroll
        for (int ntp = 0; ntp < 4; ntp++)
            ldsm4(bh[ntp], bbase + bOf[ntp] + (uint32_t)kc * 32);
        #pragma unroll
        for (int mt = 0; mt < MT; mt++)
        #pragma unroll
        for (int ntp = 0; ntp < 4; ntp++) {
            float* c0 = acc[mt * 8 + 2 * ntp];
            float* c1 = acc[mt * 8 + 2 * ntp + 1];
            mma16816(c0, ah[mt], bh[ntp]);  mma16816(c1, ah[mt], bh[ntp] + 2);
            mma16816(c0, al[mt], bh[ntp]);  mma16816(c1, al[mt], bh[ntp] + 2);
        }
    }
}

__global__ void embed_kernel(const float* __restrict__ x) {
    int idx = blockIdx.x * 256 + threadIdx.x;
    if (idx >= NIMG * 256 * 64) return;
    int c = idx & 63, px = (idx >> 6) & 255, img = idx >> 14;
    int b = img / 28, t = img % 28;
    float v = 0.f;
    if (c < 24) {
        int flat = t * 24 + c;
        v = x[((size_t)(b * 112 + flat / 6) * 256 + px) * 6 + flat % 6];
    }
    fp16 h_ = __float2half(v);
    g_xeh[idx] = h_;
    g_xel[idx] = __float2half(v - __half2float(h_));
}

__global__ void wprep_kernel(const float* __restrict__ w, fp16* __restrict__ o,
                             int IC, int ntap) {
    int idx = blockIdx.x * 256 + threadIdx.x;
    if (idx >= ntap * TAPSZ) return;
    int ic = idx & 63, n = (idx >> 6) & 255, tap = idx >> 14;
    int f = n >> 2, g = n & 3;
    int src = tap / 9, rtap = tap % 9, ics = src * 64 + ic;
    float v = (ics < IC) ? w[((size_t)rtap * IC + ics) * 256 + (g * 64 + f)] : 0.f;
    o[idx] = __float2half(v);
}

__global__ void zero_states() {
    int idx = blockIdx.x * 256 + threadIdx.x;
    if (idx == 0) g_barcnt = 0u;
    if (idx < 524288) {
        g_sth[0][idx] = __float2half(0.f);
        g_stl[0][idx] = __float2half(0.f);
        g_cst[idx] = 0.f;
    }
}

template<int NSRC>
__global__ void __launch_bounds__(256, 1) conv_mma_kernel(
    const fp16* __restrict__ s0h, const fp16* __restrict__ s0l,
    const fp16* __restrict__ s1h, const fp16* __restrict__ s1l,
    const fp16* __restrict__ wf, const fp16* __restrict__ wb,
    const float* __restrict__ bf_, const float* __restrict__ bb_) {
    extern __shared__ char sm[];
    uint32_t smb = smem_u32(sm);
    int tid = threadIdx.x, l = tid & 31, w = tid >> 5;
    int warp_m = w >> 1, warp_n = w & 1, q = l & 3;
    int img = blockIdx.x, dir = blockIdx.y, ncol = blockIdx.z;
    const fp16* wsel = dir ? wb : wf;
    const float* bias = dir ? bb_ : bf_;
    const int T = NSRC * 9;

    for (int i = tid; i < ZSZ / 16; i += 256)
        *(uint4*)(sm + i * 16) = make_uint4(0, 0, 0, 0);
    fill_A(sm, CASZ, s0h + (size_t)img * 16384, s0l + (size_t)img * 16384, 0, 18, tid);
    prefB(sm, 0, wsel, 0, ncol, tid);
    prefB(sm, 1, wsel, 1, ncol, tid);
    prefB(sm, 2, wsel, 2, ncol, tid);

    uint32_t aH[4][3], aL[4][3], bOf[4];
    mk_addrs<4>(smb, CASZ, warp_m, warp_n, l, aH, aL, bOf);
    float acc[32][4];
    #pragma unroll
    for (int i = 0; i < 32; i++)
        acc[i][0] = acc[i][1] = acc[i][2] = acc[i][3] = 0.f;

    #pragma unroll
    for (int tap = 0; tap < T; tap++) {
        if (tap < T - 2) cp_wait2(); else if (tap == T - 2) cp_wait1(); else cp_wait0();
        __syncthreads();
        if (NSRC == 2 && tap == 9) {
            fill_A(sm, CASZ, s1h + (size_t)img * 16384, s1l + (size_t)img * 16384, 0, 18, tid);
            __syncthreads();
        }
        gemm_tap2<4>(acc, aH, aL, bOf, smb + CBOFF + (tap & 3) * 18432,
                     (tap % 9) / 3, (tap % 9) % 3);
        __syncthreads();
        if (tap + 3 < T) prefB(sm, (tap + 3) & 3, wsel, tap + 3, ncol, tid);
    }

    size_t xzo = ((size_t)dir * NIMG + img) * 65536;
    #pragma unroll
    for (int mt = 0; mt < 4; mt++) {
        int m = warp_m * 64 + mt * 16 + (l >> 2);
        #pragma unroll
        for (int nt = 0; nt < 8; nt++) {
            float* c = acc[mt * 8 + nt];
            int n = ncol * 128 + warp_n * 64 + nt * 8 + q * 2;
            float b0 = __ldg(&bias[(n & 3) * 64 + (n >> 2)]);
            float b1 = __ldg(&bias[((n + 1) & 3) * 64 + ((n + 1) >> 2)]);
            *(float2*)(g_xz + xzo + (size_t)m * 256 + n) = make_float2(c[0] + b0, c[1] + b1);
            *(float2*)(g_xz + xzo + (size_t)(m + 8) * 256 + n) = make_float2(c[2] + b0, c[3] + b1);
        }
    }
}

// ------------- persistent LSTM: one launch per layer, 28 steps in-kernel ----
__global__ void __launch_bounds__(256, 1) lstm_persist_kernel(
    const fp16* __restrict__ wf, const fp16* __restrict__ wb,
    fp16* __restrict__ q0h, fp16* __restrict__ q0l,
    fp16* __restrict__ q1h, fp16* __restrict__ q1l) {
    extern __shared__ char sm[];
    uint32_t smb = smem_u32(sm);
    int tid = threadIdx.x, l = tid & 31, w = tid >> 5;
    int warp_m = w >> 1, warp_n = w & 1, q = l & 3;
    int bx = blockIdx.x;
    int dir = bx >> 6, b = (bx >> 2) & 15, hf = (bx >> 1) & 1, ncol = bx & 1;
    int dirb = dir * 16 + b;
    const fp16* wsel = dir ? wb : wf;
    const unsigned NCTA = gridDim.x;

    // weights resident for the whole layer
    prefB_all(sm, wsel, ncol, tid);
    for (int i = tid; i < ZSZ / 16; i += 256)
        *(uint4*)(sm + i * 16) = make_uint4(0, 0, 0, 0);

    uint32_t aH[2][3], aL[2][3], bOf[4];
    mk_addrs<2>(smb, LASZ, warp_m, warp_n, l, aH, aL, bOf);
    size_t ctaBase = (size_t)bx * 4096;
    bool lower = !(l & 1);
    cp_wait0();
    __syncthreads();

    for (int s = 0; s < 28; s++) {
        int t = dir ? (27 - s) : s;
        int img = b * 28 + t;

        fill_A(sm, LASZ, g_sth[s & 1] + (size_t)dirb * 16384,
               g_stl[s & 1] + (size_t)dirb * 16384, hf * 8, 10, tid);
        __syncthreads();

        float acc[16][4];
        #pragma unroll
        for (int i = 0; i < 16; i++)
            acc[i][0] = acc[i][1] = acc[i][2] = acc[i][3] = 0.f;
        #pragma unroll
        for (int t9 = 0; t9 < 9; t9++)
            gemm_tap2<2>(acc, aH, aL, bOf, smb + LBOFF + t9 * 18432, t9 / 3, t9 % 3);
        __syncthreads();

        const float* xzb = g_xz + ((size_t)dir * NIMG + img) * 65536;
        #pragma unroll
        for (int mt = 0; mt < 2; mt++) {
            int mbase = warp_m * 32 + mt * 16 + (l >> 2);
            #pragma unroll
            for (int nt = 0; nt < 8; nt++) {
                float* c = acc[mt * 8 + nt];
                float o0 = __shfl_xor_sync(0xffffffffu, c[0], 1);
                float o1 = __shfl_xor_sync(0xffffffffu, c[1], 1);
                float o2 = __shfl_xor_sync(0xffffffffu, c[2], 1);
                float o3 = __shfl_xor_sync(0xffffffffu, c[3], 1);
                float iv, fv, gv, ov;
                int m;
                if (lower) { iv = c[0]; fv = c[1]; gv = o0;  ov = o1;  m = mbase; }
                else       { iv = o2;  fv = o3;  gv = c[2]; ov = c[3]; m = mbase + 8; }
                int chp = q >> 1;
                int n4 = ncol * 128 + warp_n * 64 + nt * 8 + chp * 4;
                int pxg = hf * 128 + m;
                float4 z = *(const float4*)(xzb + (size_t)pxg * 256 + n4);
                iv = sigm(iv + z.x); fv = sigm(fv + z.y);
                gv = tanhf(gv + z.z); ov = sigm(ov + z.w);
                float* cs = g_cst + ctaBase + w * 512 + (mt * 8 + nt) * 32 + l;
                float cc = fv * (*cs) + iv * gv;
                *cs = cc;
                float hv = ov * tanhf(cc);
                fp16 hb = __float2half(hv);
                float lr = hv - __half2float(hb);
                int chc = warp_n * 16 + nt * 2 + chp;
                *(fp16*)(sm + AHI + m * 64 + chc * 2) = hb;
                *(fp16*)(sm + AHI + 8192 + m * 64 + chc * 2) = __float2half(lr);
            }
        }
        __syncthreads();

        {
            int px = tid >> 1, part = tid & 1;
            const uint4* sh_ = (const uint4*)(sm + AHI + px * 64 + part * 32);
            const uint4* sl_ = (const uint4*)(sm + AHI + 8192 + px * 64 + part * 32);
            uint4 h0 = sh_[0], h1 = sh_[1];
            uint4 l0 = sl_[0], l1 = sl_[1];
            size_t sidx = (size_t)dirb * 16384 + (size_t)(hf * 128 + px) * 64 + ncol * 32 + part * 16;
            *(uint4*)(g_sth[(s + 1) & 1] + sidx) = h0;
            *(uint4*)(g_sth[(s + 1) & 1] + sidx + 8) = h1;
            *(uint4*)(g_stl[(s + 1) & 1] + sidx) = l0;
            *(uint4*)(g_stl[(s + 1) & 1] + sidx + 8) = l1;
            fp16* qh = dir ? q1h : q0h;
            fp16* ql = dir ? q1l : q0l;
            size_t qidx = ((size_t)img * 256 + hf * 128 + px) * 64 + ncol * 32 + part * 16;
            *(uint4*)(qh + qidx) = h0;
            *(uint4*)(qh + qidx + 8) = h1;
            *(uint4*)(ql + qidx) = l0;
            *(uint4*)(ql + qidx + 8) = l1;
        }

        // device-wide barrier (all 128 CTAs co-resident; 128 <= 148 SMs)
        if (s < 27) {
            __syncthreads();
            if (tid == 0) {
                __threadfence();
                atomicAdd(&g_barcnt, 1u);
                unsigned target = (unsigned)(s + 1) * NCTA;
                volatile unsigned* bc = &g_barcnt;
                while (*bc < target) __nanosleep(64);
                __threadfence();
            }
            __syncthreads();
        }
    }
}

__global__ void __launch_bounds__(256) out_conv_kernel(
    const fp16* __restrict__ h1h0, const fp16* __restrict__ h1l0,
    const fp16* __restrict__ h1h1, const fp16* __restrict__ h1l1,
    const float* __restrict__ wout, const float* __restrict__ bout,
    float* __restrict__ out) {
    __shared__ float sh[3 * 16 * 128];
    __shared__ float ps[256];
    int n = blockIdx.x / 16, h = blockIdx.x % 16, tid = threadIdx.x;
    for (int i = tid; i < 3 * 16 * 128; i += 256) {
        int r = i / 2048, rem = i - r * 2048, c = rem >> 7, ch = rem & 127;
        int row = h - 1 + r;
        float v = 0.f;
        if (row >= 0 && row < 16) {
            size_t idx = ((size_t)n * 256 + row * 16 + c) * 64 + (ch & 63);
            if (ch < 64) v = __half2float(h1h0[idx]) + __half2float(h1l0[idx]);
            else         v = __half2float(h1h1[idx]) + __half2float(h1l1[idx]);
        }
        sh[i] = v;
    }
    __syncthreads();
    int p = tid >> 4, qq = tid & 15;
    float partial = 0.f;
    for (int kh = 0; kh < 3; kh++)
        for (int kw = 0; kw < 3; kw++) {
            int iw = p + kw - 1;
            if (iw < 0 || iw >= 16) continue;
            #pragma unroll
            for (int j = 0; j < 8; j++) {
                int ic = qq * 8 + j;
                partial += sh[(kh * 16 + iw) * 128 + ic] * wout[(kh * 3 + kw) * 128 + ic];
            }
        }
    ps[tid] = partial;
    __syncthreads();
    if (qq == 0) {
        float sum = bout[0];
        #pragma unroll
        for (int j = 0; j < 16; j++) sum += ps[p * 16 + j];
        out[((size_t)n * 16 + h) * 16 + p] = sum;
    }
}

extern "C" void kernel_launch(void* const* d_in, const int* in_sizes, int n_in,
                              void* d_out, int out_size) {
    const float* x    = (const float*)d_in[0];
    const float* wx0f = (const float*)d_in[1];
    const float* wh0f = (const float*)d_in[2];
    const float* b0f  = (const float*)d_in[3];
    const float* wx0b = (const float*)d_in[4];
    const float* wh0b = (const float*)d_in[5];
    const float* b0b  = (const float*)d_in[6];
    const float* wx1f = (const float*)d_in[7];
    const float* wh1f = (const float*)d_in[8];
    const float* b1f  = (const float*)d_in[9];
    const float* wx1b = (const float*)d_in[10];
    const float* wh1b = (const float*)d_in[11];
    const float* b1b  = (const float*)d_in[12];
    const float* wout = (const float*)d_in[13];
    const float* bout = (const float*)d_in[14];
    float* out = (float*)d_out;

    cudaFuncSetAttribute(conv_mma_kernel<1>, cudaFuncAttributeMaxDynamicSharedMemorySize, CSMEM);
    cudaFuncSetAttribute(conv_mma_kernel<2>, cudaFuncAttributeMaxDynamicSharedMemorySize, CSMEM);
    cudaFuncSetAttribute(lstm_persist_kernel, cudaFuncAttributeMaxDynamicSharedMemorySize, LSMEM);

    fp16 *wg, *xeh, *xel, *h0h0, *h0l0, *h1h0, *h1l0;
    cudaGetSymbolAddress((void**)&wg, g_w);
    cudaGetSymbolAddress((void**)&xeh, g_xeh);
    cudaGetSymbolAddress((void**)&xel, g_xel);
    cudaGetSymbolAddress((void**)&h0h0, g_h0h);
    cudaGetSymbolAddress((void**)&h0l0, g_h0l);
    cudaGetSymbolAddress((void**)&h1h0, g_h1h);
    cudaGetSymbolAddress((void**)&h1l0, g_h1l);
    const size_t HS = (size_t)NIMG * 256 * 64;
    fp16 *h0h1 = h0h0 + HS, *h0l1 = h0l0 + HS, *h1h1 = h1h0 + HS, *h1l1 = h1l0 + HS;

    wprep_kernel<<<(9*TAPSZ+255)/256, 256>>>(wx0f, wg + (size_t)0*TAPSZ,  24, 9);
    wprep_kernel<<<(9*TAPSZ+255)/256, 256>>>(wx0b, wg + (size_t)9*TAPSZ,  24, 9);
    wprep_kernel<<<(9*TAPSZ+255)/256, 256>>>(wh0f, wg + (size_t)18*TAPSZ, 64, 9);
    wprep_kernel<<<(9*TAPSZ+255)/256, 256>>>(wh0b, wg + (size_t)27*TAPSZ, 64, 9);
    wprep_kernel<<<(18*TAPSZ+255)/256, 256>>>(wx1f, wg + (size_t)36*TAPSZ, 128, 18);
    wprep_kernel<<<(18*TAPSZ+255)/256, 256>>>(wx1b, wg + (size_t)54*TAPSZ, 128, 18);
    wprep_kernel<<<(9*TAPSZ+255)/256, 256>>>(wh1f, wg + (size_t)72*TAPSZ, 64, 9);
    wprep_kernel<<<(9*TAPSZ+255)/256, 256>>>(wh1b, wg + (size_t)81*TAPSZ, 64, 9);
    embed_kernel<<<(NIMG*256*64+255)/256, 256>>>(x);

    dim3 cgrid(NIMG, 2, 2);
    conv_mma_kernel<1><<<cgrid, 256, CSMEM>>>(xeh, xel, xeh, xel,
        wg + (size_t)0*TAPSZ, wg + (size_t)9*TAPSZ, b0f, b0b);
    zero_states<<<(524288+255)/256, 256>>>();
    lstm_persist_kernel<<<128, 256, LSMEM>>>(
        wg + (size_t)18*TAPSZ, wg + (size_t)27*TAPSZ, h0h0, h0l0, h0h1, h0l1);
    conv_mma_kernel<2><<<cgrid, 256, CSMEM>>>(h0h0, h0l0, h0h1, h0l1,
        wg + (size_t)36*TAPSZ, wg + (size_t)54*TAPSZ, b1f, b1b);
    zero_states<<<(524288+255)/256, 256>>>();
    lstm_persist_kernel<<<128, 256, LSMEM>>>(
        wg + (size_t)72*TAPSZ, wg + (size_t)81*TAPSZ, h1h0, h1l0, h1h1, h1l1);

    out_conv_kernel<<<NIMG*16, 256>>>(h1h0, h1l0, h1h1, h1l1, wout, bout, out);
}

// round 8
// speedup vs baseline: 5.4267x; 1.1882x over previous
#include <cuda_runtime.h>
#include <cuda_fp16.h>
#include <stdint.h>
#include <math.h>

typedef __half fp16;

#define NIMG 448
#define TAPSZ 16384
#define ZSZ   4864
#define AHI   4864
// LSTM: A 160px x 144B hi+lo, B 9 taps x 18432
#define LASZ  23040
#define LBOFF (AHI + 2*LASZ)           // 50944
#define LSMEM (LBOFF + 9*18432)        // 216832
// conv: A 288px x 144B hi ONLY, B ring 4 x 18432
#define CASZ  41472
#define CBOFF (AHI + CASZ)             // 46336
#define CSMEM (CBOFF + 4*18432)        // 120064

__device__ fp16  g_xeh[(size_t)NIMG*256*64];
__device__ float g_xz[(size_t)2*NIMG*256*256];
__device__ fp16  g_h0h[2][(size_t)NIMG*256*64], g_h0l[2][(size_t)NIMG*256*64];
__device__ fp16  g_h1h[2][(size_t)NIMG*256*64], g_h1l[2][(size_t)NIMG*256*64];
__device__ fp16  g_sth[2][524288], g_stl[2][524288];
__device__ float g_cst[524288];
__device__ fp16  g_w[(size_t)90*TAPSZ];
__device__ unsigned g_barcnt;

__device__ __forceinline__ uint32_t smem_u32(const void* p) {
    uint32_t a;
    asm("{ .reg .u64 t; cvta.to.shared.u64 t, %1; cvt.u32.u64 %0, t; }" : "=r"(a) : "l"(p));
    return a;
}
__device__ __forceinline__ void ldsm4(uint32_t* r, uint32_t addr) {
    asm volatile("ldmatrix.sync.aligned.m8n8.x4.shared.b16 {%0,%1,%2,%3}, [%4];"
        : "=r"(r[0]), "=r"(r[1]), "=r"(r[2]), "=r"(r[3]) : "r"(addr));
}
__device__ __forceinline__ void mma16816(float* c, const uint32_t* a, const uint32_t* b) {
    asm volatile("mma.sync.aligned.m16n8k16.row.col.f32.f16.f16.f32 "
        "{%0,%1,%2,%3}, {%4,%5,%6,%7}, {%8,%9}, {%0,%1,%2,%3};"
        : "+f"(c[0]), "+f"(c[1]), "+f"(c[2]), "+f"(c[3])
        : "r"(a[0]), "r"(a[1]), "r"(a[2]), "r"(a[3]), "r"(b[0]), "r"(b[1]));
}
__device__ __forceinline__ void cpa16(uint32_t dst, const void* src) {
    asm volatile("cp.async.cg.shared.global [%0], [%1], 16;" :: "r"(dst), "l"(src) : "memory");
}
__device__ __forceinline__ void cp_commit() { asm volatile("cp.async.commit_group;" ::: "memory"); }
__device__ __forceinline__ void cp_wait2()  { asm volatile("cp.async.wait_group 2;" ::: "memory"); }
__device__ __forceinline__ void cp_wait1()  { asm volatile("cp.async.wait_group 1;" ::: "memory"); }
__device__ __forceinline__ void cp_wait0()  { asm volatile("cp.async.wait_group 0;" ::: "memory"); }
__device__ __forceinline__ float sigm(float x) { return __fdividef(1.f, 1.f + __expf(-x)); }

template<int TERMS>
__device__ __forceinline__ void fill_A(char* sm, uint32_t asz,
        const fp16* hsrc, const fp16* lsrc, int r0, int nrows, int tid) {
    const uint4* hv = (const uint4*)hsrc;
    const uint4* lv = (const uint4*)lsrc;
    const uint4 z = make_uint4(0, 0, 0, 0);
    int tot = nrows * 16 * 8;
    for (int i = tid; i < tot; i += 256) {
        int ch = i & 7, p = i >> 3;
        int hr = p >> 4, c = p & 15;
        int row = r0 - 1 + hr;
        bool v = (row >= 0 && row < 16);
        int gi = (row * 16 + c) * 8 + ch;
        uint4 hval = v ? hv[gi] : z;
        *(uint4*)(sm + AHI + p * 144 + ch * 16) = hval;
        if (TERMS == 2) {
            uint4 lval = v ? lv[gi] : z;
            *(uint4*)(sm + AHI + asz + p * 144 + ch * 16) = lval;
        }
    }
}

__device__ __forceinline__ void prefB(char* sm, uint32_t boff, int slot,
        const fp16* w, int tap, int ncol, int tid) {
    char* dh = sm + boff + slot * 18432;
    const char* g = (const char*)w + (size_t)tap * 32768 + (size_t)ncol * 16384;
    #pragma unroll
    for (int jj = 0; jj < 4; jj++) {
        int j = tid * 4 + jj;
        int row = j >> 3, of = (j & 7) * 16;
        cpa16(smem_u32(dh + row * 144 + of), g + row * 128 + of);
    }
    cp_commit();
}

__device__ __forceinline__ void prefB_all(char* sm, const fp16* w, int ncol, int tid) {
    const char* g = (const char*)w + (size_t)ncol * 16384;
    for (int i = tid; i < 9216; i += 256) {
        int tap = i >> 10, j = i & 1023;
        int row = j >> 3, of = (j & 7) * 16;
        cpa16(smem_u32(sm + LBOFF + tap * 18432 + row * 144 + of),
              g + (size_t)tap * 32768 + row * 128 + of);
    }
    cp_commit();
}

template<int MT>
__device__ __forceinline__ void mk_addrs(uint32_t smb, uint32_t asz, int warp_m,
        int warp_n, int l, uint32_t aH[][3], uint32_t aL[][3], uint32_t* bOf) {
    #pragma unroll
    for (int mt = 0; mt < MT; mt++) {
        int prow16 = warp_m * MT + mt;
        #pragma unroll
        for (int kw = 0; kw < 3; kw++) {
            int col = (l & 15) + kw - 1;
            uint32_t kpart = (uint32_t)(l >> 4) * 16;
            if ((unsigned)col > 15u) { aH[mt][kw] = smb + kpart; aL[mt][kw] = smb + kpart; }
            else {
                uint32_t base = smb + AHI + (uint32_t)(prow16 * 16 + col) * 144 + kpart;
                aH[mt][kw] = base;
                aL[mt][kw] = base + asz;
            }
        }
    }
    #pragma unroll
    for (int ntp = 0; ntp < 4; ntp++) {
        int nl = warp_n * 64 + ntp * 16 + (l & 7) + ((l >> 4) << 3);
        bOf[ntp] = (uint32_t)nl * 144 + ((l >> 3) & 1) * 16;
    }
}

template<int MT, int TERMS>
__device__ __forceinline__ void gemm_tap(float (*acc)[4],
        const uint32_t aH[][3], const uint32_t aL[][3], const uint32_t* bOf,
        uint32_t bbase, int kh, int kw) {
    uint32_t akk = (uint32_t)kh * 2304;
    #pragma unroll
    for (int kc = 0; kc < 4; kc++) {
        uint32_t ko = akk + (uint32_t)kc * 32;
        uint32_t ah[MT][4], al[MT][4], bh[4][4];
        #pragma unroll
        for (int mt = 0; mt < MT; mt++) {
            ldsm4(ah[mt], aH[mt][kw] + ko);
            if (TERMS == 2) ldsm4(al[mt], aL[mt][kw] + ko);
        }
        #pragma unroll
        for (int ntp = 0; ntp < 4; ntp++)
            ldsm4(bh[ntp], bbase + bOf[ntp] + (uint32_t)kc * 32);
        #pragma unroll
        for (int mt = 0; mt < MT; mt++)
        #pragma unroll
        for (int ntp = 0; ntp < 4; ntp++) {
            float* c0 = acc[mt * 8 + 2 * ntp];
            float* c1 = acc[mt * 8 + 2 * ntp + 1];
            mma16816(c0, ah[mt], bh[ntp]);  mma16816(c1, ah[mt], bh[ntp] + 2);
            if (TERMS == 2) {
                mma16816(c0, al[mt], bh[ntp]);  mma16816(c1, al[mt], bh[ntp] + 2);
            }
        }
    }
}

__global__ void embed_kernel(const float* __restrict__ x) {
    int idx = blockIdx.x * 256 + threadIdx.x;
    if (idx >= NIMG * 256 * 64) return;
    int c = idx & 63, px = (idx >> 6) & 255, img = idx >> 14;
    int b = img / 28, t = img % 28;
    float v = 0.f;
    if (c < 24) {
        int flat = t * 24 + c;
        v = x[((size_t)(b * 112 + flat / 6) * 256 + px) * 6 + flat % 6];
    }
    g_xeh[idx] = __float2half(v);
}

__global__ void wprep_kernel(const float* __restrict__ w, fp16* __restrict__ o,
                             int IC, int ntap) {
    int idx = blockIdx.x * 256 + threadIdx.x;
    if (idx >= ntap * TAPSZ) return;
    int ic = idx & 63, n = (idx >> 6) & 255, tap = idx >> 14;
    int f = n >> 2, g = n & 3;
    int src = tap / 9, rtap = tap % 9, ics = src * 64 + ic;
    float v = (ics < IC) ? w[((size_t)rtap * IC + ics) * 256 + (g * 64 + f)] : 0.f;
    o[idx] = __float2half(v);
}

__global__ void zero_states() {
    int idx = blockIdx.x * 256 + threadIdx.x;
    if (idx == 0) g_barcnt = 0u;
    if (idx < 524288) {
        g_sth[0][idx] = __float2half(0.f);
        g_stl[0][idx] = __float2half(0.f);
        g_cst[idx] = 0.f;
    }
}

// feed-forward convs: single-term A (fp16), half the MMAs
template<int NSRC>
__global__ void __launch_bounds__(256, 1) conv_mma_kernel(
    const fp16* __restrict__ s0h, const fp16* __restrict__ s1h,
    const fp16* __restrict__ wf, const fp16* __restrict__ wb,
    const float* __restrict__ bf_, const float* __restrict__ bb_) {
    extern __shared__ char sm[];
    uint32_t smb = smem_u32(sm);
    int tid = threadIdx.x, l = tid & 31, w = tid >> 5;
    int warp_m = w >> 1, warp_n = w & 1, q = l & 3;
    int img = blockIdx.x, dir = blockIdx.y, ncol = blockIdx.z;
    const fp16* wsel = dir ? wb : wf;
    const float* bias = dir ? bb_ : bf_;
    const int T = NSRC * 9;

    for (int i = tid; i < ZSZ / 16; i += 256)
        *(uint4*)(sm + i * 16) = make_uint4(0, 0, 0, 0);
    fill_A<1>(sm, CASZ, s0h + (size_t)img * 16384, (const fp16*)0, 0, 18, tid);
    prefB(sm, CBOFF, 0, wsel, 0, ncol, tid);
    prefB(sm, CBOFF, 1, wsel, 1, ncol, tid);
    prefB(sm, CBOFF, 2, wsel, 2, ncol, tid);

    uint32_t aH[4][3], aL[4][3], bOf[4];
    mk_addrs<4>(smb, CASZ, warp_m, warp_n, l, aH, aL, bOf);
    float acc[32][4];
    #pragma unroll
    for (int i = 0; i < 32; i++)
        acc[i][0] = acc[i][1] = acc[i][2] = acc[i][3] = 0.f;

    #pragma unroll
    for (int tap = 0; tap < T; tap++) {
        if (tap < T - 2) cp_wait2(); else if (tap == T - 2) cp_wait1(); else cp_wait0();
        __syncthreads();
        if (NSRC == 2 && tap == 9) {
            fill_A<1>(sm, CASZ, s1h + (size_t)img * 16384, (const fp16*)0, 0, 18, tid);
            __syncthreads();
        }
        gemm_tap<4, 1>(acc, aH, aL, bOf, smb + CBOFF + (tap & 3) * 18432,
                       (tap % 9) / 3, (tap % 9) % 3);
        __syncthreads();
        if (tap + 3 < T) prefB(sm, CBOFF, (tap + 3) & 3, wsel, tap + 3, ncol, tid);
    }

    size_t xzo = ((size_t)dir * NIMG + img) * 65536;
    #pragma unroll
    for (int mt = 0; mt < 4; mt++) {
        int m = warp_m * 64 + mt * 16 + (l >> 2);
        #pragma unroll
        for (int nt = 0; nt < 8; nt++) {
            float* c = acc[mt * 8 + nt];
            int n = ncol * 128 + warp_n * 64 + nt * 8 + q * 2;
            float b0 = __ldg(&bias[(n & 3) * 64 + (n >> 2)]);
            float b1 = __ldg(&bias[((n + 1) & 3) * 64 + ((n + 1) >> 2)]);
            *(float2*)(g_xz + xzo + (size_t)m * 256 + n) = make_float2(c[0] + b0, c[1] + b1);
            *(float2*)(g_xz + xzo + (size_t)(m + 8) * 256 + n) = make_float2(c[2] + b0, c[3] + b1);
        }
    }
}

// persistent LSTM: hi/lo state preserved (recurrent error compounds)
__global__ void __launch_bounds__(256, 1) lstm_persist_kernel(
    const fp16* __restrict__ wf, const fp16* __restrict__ wb,
    fp16* __restrict__ q0h, fp16* __restrict__ q0l,
    fp16* __restrict__ q1h, fp16* __restrict__ q1l) {
    extern __shared__ char sm[];
    uint32_t smb = smem_u32(sm);
    int tid = threadIdx.x, l = tid & 31, w = tid >> 5;
    int warp_m = w >> 1, warp_n = w & 1, q = l & 3;
    int bx = blockIdx.x;
    int dir = bx >> 6, b = (bx >> 2) & 15, hf = (bx >> 1) & 1, ncol = bx & 1;
    int dirb = dir * 16 + b;
    const fp16* wsel = dir ? wb : wf;
    const unsigned NCTA = gridDim.x;

    prefB_all(sm, wsel, ncol, tid);
    for (int i = tid; i < ZSZ / 16; i += 256)
        *(uint4*)(sm + i * 16) = make_uint4(0, 0, 0, 0);

    uint32_t aH[2][3], aL[2][3], bOf[4];
    mk_addrs<2>(smb, LASZ, warp_m, warp_n, l, aH, aL, bOf);
    size_t ctaBase = (size_t)bx * 4096;
    bool lower = !(l & 1);
    cp_wait0();
    __syncthreads();

    for (int s = 0; s < 28; s++) {
        int t = dir ? (27 - s) : s;
        int img = b * 28 + t;

        fill_A<2>(sm, LASZ, g_sth[s & 1] + (size_t)dirb * 16384,
                  g_stl[s & 1] + (size_t)dirb * 16384, hf * 8, 10, tid);
        __syncthreads();

        float acc[16][4];
        #pragma unroll
        for (int i = 0; i < 16; i++)
            acc[i][0] = acc[i][1] = acc[i][2] = acc[i][3] = 0.f;
        #pragma unroll
        for (int t9 = 0; t9 < 9; t9++)
            gemm_tap<2, 2>(acc, aH, aL, bOf, smb + LBOFF + t9 * 18432, t9 / 3, t9 % 3);
        __syncthreads();

        const float* xzb = g_xz + ((size_t)dir * NIMG + img) * 65536;
        #pragma unroll
        for (int mt = 0; mt < 2; mt++) {
            int mbase = warp_m * 32 + mt * 16 + (l >> 2);
            #pragma unroll
            for (int nt = 0; nt < 8; nt++) {
                float* c = acc[mt * 8 + nt];
                float o0 = __shfl_xor_sync(0xffffffffu, c[0], 1);
                float o1 = __shfl_xor_sync(0xffffffffu, c[1], 1);
                float o2 = __shfl_xor_sync(0xffffffffu, c[2], 1);
                float o3 = __shfl_xor_sync(0xffffffffu, c[3], 1);
                float iv, fv, gv, ov;
                int m;
                if (lower) { iv = c[0]; fv = c[1]; gv = o0;  ov = o1;  m = mbase; }
                else       { iv = o2;  fv = o3;  gv = c[2]; ov = c[3]; m = mbase + 8; }
                int chp = q >> 1;
                int n4 = ncol * 128 + warp_n * 64 + nt * 8 + chp * 4;
                int pxg = hf * 128 + m;
                float4 z = *(const float4*)(xzb + (size_t)pxg * 256 + n4);
                iv = sigm(iv + z.x); fv = sigm(fv + z.y);
                gv = tanhf(gv + z.z); ov = sigm(ov + z.w);
                float* cs = g_cst + ctaBase + w * 512 + (mt * 8 + nt) * 32 + l;
                float cc = fv * (*cs) + iv * gv;
                *cs = cc;
                float hv = ov * tanhf(cc);
                fp16 hb = __float2half(hv);
                float lr = hv - __half2float(hb);
                int chc = warp_n * 16 + nt * 2 + chp;
                *(fp16*)(sm + AHI + m * 64 + chc * 2) = hb;
                *(fp16*)(sm + AHI + 8192 + m * 64 + chc * 2) = __float2half(lr);
            }
        }
        __syncthreads();

        {
            int px = tid >> 1, part = tid & 1;
            const uint4* sh_ = (const uint4*)(sm + AHI + px * 64 + part * 32);
            const uint4* sl_ = (const uint4*)(sm + AHI + 8192 + px * 64 + part * 32);
            uint4 h0 = sh_[0], h1 = sh_[1];
            uint4 l0 = sl_[0], l1 = sl_[1];
            size_t sidx = (size_t)dirb * 16384 + (size_t)(hf * 128 + px) * 64 + ncol * 32 + part * 16;
            *(uint4*)(g_sth[(s + 1) & 1] + sidx) = h0;
            *(uint4*)(g_sth[(s + 1) & 1] + sidx + 8) = h1;
            *(uint4*)(g_stl[(s + 1) & 1] + sidx) = l0;
            *(uint4*)(g_stl[(s + 1) & 1] + sidx + 8) = l1;
            fp16* qh = dir ? q1h : q0h;
            fp16* ql = dir ? q1l : q0l;
            size_t qidx = ((size_t)img * 256 + hf * 128 + px) * 64 + ncol * 32 + part * 16;
            *(uint4*)(qh + qidx) = h0;
            *(uint4*)(qh + qidx + 8) = h1;
            *(uint4*)(ql + qidx) = l0;
            *(uint4*)(ql + qidx + 8) = l1;
        }

        if (s < 27) {
            __syncthreads();
            if (tid == 0) {
                __threadfence();
                atomicAdd(&g_barcnt, 1u);
                unsigned target = (unsigned)(s + 1) * NCTA;
                volatile unsigned* bc = &g_barcnt;
                while (*bc < target) __nanosleep(64);
                __threadfence();
            }
            __syncthreads();
        }
    }
}

__global__ void __launch_bounds__(256) out_conv_kernel(
    const fp16* __restrict__ h1h0, const fp16* __restrict__ h1l0,
    const fp16* __restrict__ h1h1, const fp16* __restrict__ h1l1,
    const float* __restrict__ wout, const float* __restrict__ bout,
    float* __restrict__ out) {
    __shared__ float sh[3 * 16 * 128];
    __shared__ float ps[256];
    int n = blockIdx.x / 16, h = blockIdx.x % 16, tid = threadIdx.x;
    for (int i = tid; i < 3 * 16 * 128; i += 256) {
        int r = i / 2048, rem = i - r * 2048, c = rem >> 7, ch = rem & 127;
        int row = h - 1 + r;
        float v = 0.f;
        if (row >= 0 && row < 16) {
            size_t idx = ((size_t)n * 256 + row * 16 + c) * 64 + (ch & 63);
            if (ch < 64) v = __half2float(h1h0[idx]) + __half2float(h1l0[idx]);
            else         v = __half2float(h1h1[idx]) + __half2float(h1l1[idx]);
        }
        sh[i] = v;
    }
    __syncthreads();
    int p = tid >> 4, qq = tid & 15;
    float partial = 0.f;
    for (int kh = 0; kh < 3; kh++)
        for (int kw = 0; kw < 3; kw++) {
            int iw = p + kw - 1;
            if (iw < 0 || iw >= 16) continue;
            #pragma unroll
            for (int j = 0; j < 8; j++) {
                int ic = qq * 8 + j;
                partial += sh[(kh * 16 + iw) * 128 + ic] * wout[(kh * 3 + kw) * 128 + ic];
            }
        }
    ps[tid] = partial;
    __syncthreads();
    if (qq == 0) {
        float sum = bout[0];
        #pragma unroll
        for (int j = 0; j < 16; j++) sum += ps[p * 16 + j];
        out[((size_t)n * 16 + h) * 16 + p] = sum;
    }
}

extern "C" void kernel_launch(void* const* d_in, const int* in_sizes, int n_in,
                              void* d_out, int out_size) {
    const float* x    = (const float*)d_in[0];
    const float* wx0f = (const float*)d_in[1];
    const float* wh0f = (const float*)d_in[2];
    const float* b0f  = (const float*)d_in[3];
    const float* wx0b = (const float*)d_in[4];
    const float* wh0b = (const float*)d_in[5];
    const float* b0b  = (const float*)d_in[6];
    const float* wx1f = (const float*)d_in[7];
    const float* wh1f = (const float*)d_in[8];
    const float* b1f  = (const float*)d_in[9];
    const float* wx1b = (const float*)d_in[10];
    const float* wh1b = (const float*)d_in[11];
    const float* b1b  = (const float*)d_in[12];
    const float* wout = (const float*)d_in[13];
    const float* bout = (const float*)d_in[14];
    float* out = (float*)d_out;

    cudaFuncSetAttribute(conv_mma_kernel<1>, cudaFuncAttributeMaxDynamicSharedMemorySize, CSMEM);
    cudaFuncSetAttribute(conv_mma_kernel<2>, cudaFuncAttributeMaxDynamicSharedMemorySize, CSMEM);
    cudaFuncSetAttribute(lstm_persist_kernel, cudaFuncAttributeMaxDynamicSharedMemorySize, LSMEM);

    fp16 *wg, *xeh, *h0h0, *h0l0, *h1h0, *h1l0;
    cudaGetSymbolAddress((void**)&wg, g_w);
    cudaGetSymbolAddress((void**)&xeh, g_xeh);
    cudaGetSymbolAddress((void**)&h0h0, g_h0h);
    cudaGetSymbolAddress((void**)&h0l0, g_h0l);
    cudaGetSymbolAddress((void**)&h1h0, g_h1h);
    cudaGetSymbolAddress((void**)&h1l0, g_h1l);
    const size_t HS = (size_t)NIMG * 256 * 64;
    fp16 *h0h1 = h0h0 + HS, *h0l1 = h0l0 + HS, *h1h1 = h1h0 + HS, *h1l1 = h1l0 + HS;

    wprep_kernel<<<(9*TAPSZ+255)/256, 256>>>(wx0f, wg + (size_t)0*TAPSZ,  24, 9);
    wprep_kernel<<<(9*TAPSZ+255)/256, 256>>>(wx0b, wg + (size_t)9*TAPSZ,  24, 9);
    wprep_kernel<<<(9*TAPSZ+255)/256, 256>>>(wh0f, wg + (size_t)18*TAPSZ, 64, 9);
    wprep_kernel<<<(9*TAPSZ+255)/256, 256>>>(wh0b, wg + (size_t)27*TAPSZ, 64, 9);
    wprep_kernel<<<(18*TAPSZ+255)/256, 256>>>(wx1f, wg + (size_t)36*TAPSZ, 128, 18);
    wprep_kernel<<<(18*TAPSZ+255)/256, 256>>>(wx1b, wg + (size_t)54*TAPSZ, 128, 18);
    wprep_kernel<<<(9*TAPSZ+255)/256, 256>>>(wh1f, wg + (size_t)72*TAPSZ, 64, 9);
    wprep_kernel<<<(9*TAPSZ+255)/256, 256>>>(wh1b, wg + (size_t)81*TAPSZ, 64, 9);
    embed_kernel<<<(NIMG*256*64+255)/256, 256>>>(x);

    dim3 cgrid(NIMG, 2, 2);
    conv_mma_kernel<1><<<cgrid, 256, CSMEM>>>(xeh, xeh,
        wg + (size_t)0*TAPSZ, wg + (size_t)9*TAPSZ, b0f, b0b);
    zero_states<<<(524288+255)/256, 256>>>();
    lstm_persist_kernel<<<128, 256, LSMEM>>>(
        wg + (size_t)18*TAPSZ, wg + (size_t)27*TAPSZ, h0h0, h0l0, h0h1, h0l1);
    conv_mma_kernel<2><<<cgrid, 256, CSMEM>>>(h0h0, h0h1,
        wg + (size_t)36*TAPSZ, wg + (size_t)54*TAPSZ, b1f, b1b);
    zero_states<<<(524288+255)/256, 256>>>();
    lstm_persist_kernel<<<128, 256, LSMEM>>>(
        wg + (size_t)72*TAPSZ, wg + (size_t)81*TAPSZ, h1h0, h1l0, h1h1, h1l1);

    out_conv_kernel<<<NIMG*16, 256>>>(h1h0, h1l0, h1h1, h1l1, wout, bout, out);
}